// round 14
// baseline (speedup 1.0000x reference)
#include <cuda_runtime.h>
#include <math.h>

#define B_   128
#define T_   400
#define E_   512
#define ENC_ 512
#define DEC_ 1024
#define NM_  80
#define A_   128
#define H_   256
#define T3_  1200
#define KZ_  1792
#define BT3  (B_*T3_)

typedef unsigned long long ull;

__device__ __align__(16) float g_h0 [T_*B_*ENC_];
__device__ __align__(16) float g_hB [T_*B_*ENC_];
__device__ __align__(16) float g_Xf [T_*B_*1024];
__device__ __align__(16) float g_Xb [T_*B_*1024];
__device__ __align__(16) float g_hst[2*2*B_*H_];
__device__ __align__(16) float g_cst[2*B_*H_];
__device__ float g_mean[512], g_istd[512];
__device__ __align__(16) float g_pm [T_*B_*A_];
__device__ __align__(16) float g_zin[B_*KZ_];
__device__ __align__(16) float g_hd [B_*DEC_];
__device__ __align__(16) float g_cd [2*B_*DEC_];
__device__ __align__(16) float g_Wc [4096*KZ_];
__device__ float g_wl2[A_*31];
__device__ __align__(16) float g_post[(size_t)512*BT3];
__device__ __align__(16) float g_WqT[1024*128];
__device__ __align__(16) float g_W1T[80*256];
__device__ __align__(16) float g_W2T[256*256];
__device__ __align__(16) float g_oWT[1536*240];

__device__ unsigned long long g_bcL[2] = {0ull, 0ull};
__device__ unsigned long long g_bc128 = 0ull;

__device__ __forceinline__ float sigm(float x){ return 1.f/(1.f+__expf(-x)); }
__device__ __forceinline__ float ftanh(float x){ float e = __expf(2.f*x); return 1.f - 2.f/(e+1.f); }

__device__ __forceinline__ ull pack2(float x){
  ull r; unsigned u = __float_as_uint(x);
  asm("mov.b64 %0, {%1, %1};" : "=l"(r) : "r"(u));
  return r;
}
__device__ __forceinline__ void fma2(ull& d, ull a, ull b){
  asm("fma.rn.f32x2 %0, %1, %2, %0;" : "+l"(d) : "l"(a), "l"(b));
}
__device__ __forceinline__ void unp2(float& lo, float& hi, ull v){
  unsigned a, b;
  asm("mov.b64 {%0, %1}, %2;" : "=r"(a), "=r"(b) : "l"(v));
  lo = __uint_as_float(a); hi = __uint_as_float(b);
}

__device__ __forceinline__ void gbar(unsigned long long* cnt, unsigned nb){
  __syncthreads();
  if (threadIdx.x == 0){
    __threadfence();
    unsigned long long my = atomicAdd(cnt, 1ull) + 1ull;
    unsigned long long target = ((my + nb - 1ull)/nb)*nb;
    while (*(volatile unsigned long long*)cnt < target) { }
    __threadfence();
  }
  __syncthreads();
}

#define OUTER4(a, bv) \
  acc[0][0]+=a.x*bv.x; acc[0][1]+=a.x*bv.y; acc[0][2]+=a.x*bv.z; acc[0][3]+=a.x*bv.w; \
  acc[1][0]+=a.y*bv.x; acc[1][1]+=a.y*bv.y; acc[1][2]+=a.y*bv.z; acc[1][3]+=a.y*bv.w; \
  acc[2][0]+=a.z*bv.x; acc[2][1]+=a.z*bv.y; acc[2][2]+=a.z*bv.z; acc[2][3]+=a.z*bv.w; \
  acc[3][0]+=a.w*bv.x; acc[3][1]+=a.w*bv.y; acc[3][2]+=a.w*bv.z; acc[3][3]+=a.w*bv.w;

#define POUTER4G(ac, am, bv) { \
  ull b0p=pack2(bv.x), b1p=pack2(bv.y), b2p=pack2(bv.z), b3p=pack2(bv.w); \
  fma2(ac[0][0], am.x, b0p); fma2(ac[0][1], am.y, b0p); \
  fma2(ac[1][0], am.x, b1p); fma2(ac[1][1], am.y, b1p); \
  fma2(ac[2][0], am.x, b2p); fma2(ac[2][1], am.y, b2p); \
  fma2(ac[3][0], am.x, b3p); fma2(ac[3][1], am.y, b3p); }

__global__ void k_transp(const float* __restrict__ s, float* __restrict__ d, int R, int C){
  int i = blockIdx.x*256 + threadIdx.x;
  if (i < R*C){ int r = i/C, c = i - r*C; d[c*R + r] = s[i]; }
}

// ---------------- encoder conv ----------
__global__ void k_conv_enc(const int* __restrict__ text, const float* __restrict__ emb,
                           const float* __restrict__ w, const float* __restrict__ bias,
                           float* __restrict__ outp){
  const int col0 = blockIdx.x*64, o0 = blockIdx.y*64;
  const int tid = threadIdx.x, tx = tid&15, ty = tid>>4;
  __shared__ int stok[64][5];
  __shared__ __align__(16) float As[16][64];
  __shared__ __align__(16) float Bs[16][64];
  for (int i = tid; i < 320; i += 256){
    int cl = i/5, k = i - cl*5;
    int col = col0 + cl, b = col/T_, t = col - b*T_;
    int tp = t + k - 2;
    stok[cl][k] = (tp >= 0 && tp < T_) ? text[b*T_ + tp] : -1;
  }
  float acc[4][4] = {};
  const int lr = tid & 63, kg = tid >> 6;
  __syncthreads();
  for (int kc = 0; kc < E_*5; kc += 16){
    float4 a4 = *(const float4*)&w[(size_t)(o0+lr)*(E_*5) + kc + kg*4];
    As[kg*4+0][lr]=a4.x; As[kg*4+1][lr]=a4.y; As[kg*4+2][lr]=a4.z; As[kg*4+3][lr]=a4.w;
    #pragma unroll
    for (int q = 0; q < 4; q++){
      int e = tid + q*256, r = e>>6, cl = e&63;
      int rg = kc + r, ii = rg/5, k = rg - ii*5;
      int tok = stok[cl][k];
      Bs[r][cl] = (tok >= 0) ? emb[tok*E_ + ii] : 0.f;
    }
    __syncthreads();
    #pragma unroll
    for (int kk = 0; kk < 16; kk++){
      float4 a  = *(const float4*)&As[kk][ty*4];
      float4 bv = *(const float4*)&Bs[kk][tx*4];
      OUTER4(a, bv);
    }
    __syncthreads();
  }
  float b0v=bias[o0+ty*4+0], b1v=bias[o0+ty*4+1], b2v=bias[o0+ty*4+2], b3v=bias[o0+ty*4+3];
  #pragma unroll
  for (int j = 0; j < 4; j++){
    int col = col0 + tx*4 + j, b = col/T_, t = col - b*T_;
    float4 v;
    v.x = fmaxf(acc[0][j]+b0v, 0.f);
    v.y = fmaxf(acc[1][j]+b1v, 0.f);
    v.z = fmaxf(acc[2][j]+b2v, 0.f);
    v.w = fmaxf(acc[3][j]+b3v, 0.f);
    *(float4*)&outp[(size_t)(t*B_+b)*ENC_ + o0 + ty*4] = v;
  }
}

// ---------------- encoder BN (channel-last, unchanged numerics) ----------
__global__ void k_bn_stats(const float* __restrict__ x, float* mean, float* istd, int rows){
  int o = blockIdx.x, tid = threadIdx.x;
  float s = 0.f, ss = 0.f;
  for (int r = tid; r < rows; r += 256){
    float v = x[(size_t)r*512 + o]; s += v; ss += v*v;
  }
  __shared__ float rs[256], rq[256];
  rs[tid]=s; rq[tid]=ss; __syncthreads();
  for (int st = 128; st; st >>= 1){
    if (tid < st){ rs[tid]+=rs[tid+st]; rq[tid]+=rq[tid+st]; }
    __syncthreads();
  }
  if (tid == 0){
    float m = rs[0]/(float)rows;
    float var = rq[0]/(float)rows - m*m;
    mean[o] = m; istd[o] = rsqrtf(var + 1e-5f);
  }
}
__global__ void k_bn_norm(float* x, const float* mean, const float* istd,
                          const float* g, const float* bt, size_t n){
  size_t i = (size_t)blockIdx.x*256 + threadIdx.x, s = (size_t)gridDim.x*256;
  for (; i < n; i += s){
    int o = (int)(i & 511);
    x[i] = (x[i]-mean[o])*istd[o]*g[o] + bt[o];
  }
}

// ---------------- postnet BN (channel-major, coalesced) ----------
__global__ void k_bn_stats_cm(const float* __restrict__ x, float* mean, float* istd){
  int o = blockIdx.x, tid = threadIdx.x;
  const float* row = x + (size_t)o*BT3;
  float s = 0.f, ss = 0.f;
  for (int i = tid; i < BT3; i += 256){ float v = row[i]; s += v; ss += v*v; }
  __shared__ float rs[256], rq[256];
  rs[tid]=s; rq[tid]=ss; __syncthreads();
  for (int st = 128; st; st >>= 1){
    if (tid < st){ rs[tid]+=rs[tid+st]; rq[tid]+=rq[tid+st]; }
    __syncthreads();
  }
  if (tid == 0){
    float m = rs[0]/(float)BT3;
    float var = rq[0]/(float)BT3 - m*m;
    mean[o] = m; istd[o] = rsqrtf(var + 1e-5f);
  }
}
__global__ void k_bn_norm_cm(float* x, const float* mean, const float* istd,
                             const float* g, const float* bt){
  int o = blockIdx.y;
  int i = blockIdx.x*256 + threadIdx.x;
  if (i < BT3){
    size_t idx = (size_t)o*BT3 + i;
    float v = (x[idx]-mean[o])*istd[o]*g[o] + bt[o];
    x[idx] = ftanh(v);
  }
}

// ---------------- SGEMM (f32x2 packed): C[M,N] = A@W^T (+bias) ------
__global__ void k_sgemm(const float* __restrict__ Am, const float* __restrict__ Wm,
                        const float* __restrict__ bias, float* __restrict__ C,
                        int M, int N, int K){
  int m0 = blockIdx.x*64, n0 = blockIdx.y*64;
  int tid = threadIdx.x, tx = tid&15, ty = tid>>4;
  __shared__ __align__(16) float As[16][64];
  __shared__ __align__(16) float Ws[16][64];
  ull ac2[4][2];
  #pragma unroll
  for (int i=0;i<4;i++){ ac2[i][0]=0ull; ac2[i][1]=0ull; }
  int lr = tid & 63, kg = tid >> 6;
  float4 pa = *(const float4*)&Am[(size_t)(m0+lr)*K + kg*4];
  float4 pw = *(const float4*)&Wm[(size_t)(n0+lr)*K + kg*4];
  for (int kc = 0; kc < K; kc += 16){
    As[kg*4+0][lr]=pa.x; As[kg*4+1][lr]=pa.y; As[kg*4+2][lr]=pa.z; As[kg*4+3][lr]=pa.w;
    Ws[kg*4+0][lr]=pw.x; Ws[kg*4+1][lr]=pw.y; Ws[kg*4+2][lr]=pw.z; Ws[kg*4+3][lr]=pw.w;
    __syncthreads();
    if (kc + 16 < K){
      pa = *(const float4*)&Am[(size_t)(m0+lr)*K + kc+16 + kg*4];
      pw = *(const float4*)&Wm[(size_t)(n0+lr)*K + kc+16 + kg*4];
    }
    #pragma unroll
    for (int kk = 0; kk < 16; kk++){
      ulonglong2 am = *(const ulonglong2*)&As[kk][ty*4];
      float4 bv = *(const float4*)&Ws[kk][tx*4];
      POUTER4G(ac2, am, bv);
    }
    __syncthreads();
  }
  float bb[4] = {0,0,0,0};
  if (bias){ bb[0]=bias[n0+tx*4+0]; bb[1]=bias[n0+tx*4+1]; bb[2]=bias[n0+tx*4+2]; bb[3]=bias[n0+tx*4+3]; }
  float r[4][4];
  #pragma unroll
  for (int j = 0; j < 4; j++){
    unp2(r[0][j], r[1][j], ac2[j][0]);
    unp2(r[2][j], r[3][j], ac2[j][1]);
  }
  #pragma unroll
  for (int i = 0; i < 4; i++){
    float4 v; v.x=r[i][0]+bb[0]; v.y=r[i][1]+bb[1]; v.z=r[i][2]+bb[2]; v.w=r[i][3]+bb[3];
    *(float4*)&C[(size_t)(m0+ty*4+i)*N + n0 + tx*4] = v;
  }
}

// ---------------- dual SGEMM: shares A-tile for fwd+bwd LSTM input ------
__global__ void k_sgemm_dual(const float* __restrict__ Am,
                             const float* __restrict__ Wf, const float* __restrict__ bf, float* __restrict__ Cf,
                             const float* __restrict__ Wb, const float* __restrict__ bb_, float* __restrict__ Cb){
  const int K = 512, N = 1024;
  int m0 = blockIdx.x*64, n0 = blockIdx.y*64;
  int tid = threadIdx.x, tx = tid&15, ty = tid>>4;
  __shared__ __align__(16) float As[16*64];
  __shared__ __align__(16) float Wsf[16*64];
  __shared__ __align__(16) float Wsb[16*64];
  ull acf[4][2], acb[4][2];
  #pragma unroll
  for (int i=0;i<4;i++){ acf[i][0]=0; acf[i][1]=0; acb[i][0]=0; acb[i][1]=0; }
  int lr = tid & 63, kg = tid >> 6;
  float4 pa = *(const float4*)&Am[(size_t)(m0+lr)*K + kg*4];
  float4 pf = *(const float4*)&Wf[(size_t)(n0+lr)*K + kg*4];
  float4 pb = *(const float4*)&Wb[(size_t)(n0+lr)*K + kg*4];
  for (int kc = 0; kc < K; kc += 16){
    As [(kg*4+0)*64+lr]=pa.x; As [(kg*4+1)*64+lr]=pa.y; As [(kg*4+2)*64+lr]=pa.z; As [(kg*4+3)*64+lr]=pa.w;
    Wsf[(kg*4+0)*64+lr]=pf.x; Wsf[(kg*4+1)*64+lr]=pf.y; Wsf[(kg*4+2)*64+lr]=pf.z; Wsf[(kg*4+3)*64+lr]=pf.w;
    Wsb[(kg*4+0)*64+lr]=pb.x; Wsb[(kg*4+1)*64+lr]=pb.y; Wsb[(kg*4+2)*64+lr]=pb.z; Wsb[(kg*4+3)*64+lr]=pb.w;
    __syncthreads();
    if (kc + 16 < K){
      pa = *(const float4*)&Am[(size_t)(m0+lr)*K + kc+16 + kg*4];
      pf = *(const float4*)&Wf[(size_t)(n0+lr)*K + kc+16 + kg*4];
      pb = *(const float4*)&Wb[(size_t)(n0+lr)*K + kc+16 + kg*4];
    }
    #pragma unroll
    for (int kk = 0; kk < 16; kk++){
      ulonglong2 am = *(const ulonglong2*)&As[kk*64 + ty*4];
      float4 bvf = *(const float4*)&Wsf[kk*64 + tx*4];
      POUTER4G(acf, am, bvf);
      float4 bvb = *(const float4*)&Wsb[kk*64 + tx*4];
      POUTER4G(acb, am, bvb);
    }
    __syncthreads();
  }
  float bfv[4] = {bf[n0+tx*4+0], bf[n0+tx*4+1], bf[n0+tx*4+2], bf[n0+tx*4+3]};
  float bbv[4] = {bb_[n0+tx*4+0], bb_[n0+tx*4+1], bb_[n0+tx*4+2], bb_[n0+tx*4+3]};
  float rf[4][4], rb[4][4];
  #pragma unroll
  for (int j = 0; j < 4; j++){
    unp2(rf[0][j], rf[1][j], acf[j][0]); unp2(rf[2][j], rf[3][j], acf[j][1]);
    unp2(rb[0][j], rb[1][j], acb[j][0]); unp2(rb[2][j], rb[3][j], acb[j][1]);
  }
  #pragma unroll
  for (int i = 0; i < 4; i++){
    float4 v1; v1.x=rf[i][0]+bfv[0]; v1.y=rf[i][1]+bfv[1]; v1.z=rf[i][2]+bfv[2]; v1.w=rf[i][3]+bfv[3];
    *(float4*)&Cf[(size_t)(m0+ty*4+i)*N + n0 + tx*4] = v1;
    float4 v2; v2.x=rb[i][0]+bbv[0]; v2.y=rb[i][1]+bbv[1]; v2.z=rb[i][2]+bbv[2]; v2.w=rb[i][3]+bbv[3];
    *(float4*)&Cb[(size_t)(m0+ty*4+i)*N + n0 + tx*4] = v2;
  }
}

// ---------------- persistent biLSTM layer (per-dir barriers) ----------
__global__ void k_lstm_layer(const float* __restrict__ Xf, const float* __restrict__ Xb,
                             const float* __restrict__ Whh_base,
                             float* __restrict__ hst, float* __restrict__ cst,
                             float* __restrict__ hout){
  const int jt = blockIdx.x, bt = blockIdx.y, dir = blockIdx.z;
  const int tid = threadIdx.x, tx = tid&15, ty = tid>>4;
  const int b0 = bt*64, j0 = jt*16;
  const float* Whh = Whh_base + (size_t)dir*4*H_*H_;
  const float* Xg  = dir ? Xb : Xf;
  __shared__ __align__(16) float hs[16][64];
  __shared__ __align__(16) float ws[16][64];
  const int lr = tid & 63, kg = tid >> 6;
  const int wrow = (lr&3)*H_ + j0 + (lr>>2);

  for (int i = tid; i < 64*16; i += 256){
    int bb = b0 + (i>>4), j = j0 + (i&15);
    hst[(size_t)(0*2+dir)*B_*H_ + bb*H_ + j] = 0.f;
    hst[(size_t)(1*2+dir)*B_*H_ + bb*H_ + j] = 0.f;
    cst[(size_t)dir*B_*H_ + bb*H_ + j] = 0.f;
  }
  gbar(&g_bcL[dir], 32);

  for (int t = 0; t < T_; t++){
    const float* hprev = hst + (size_t)((t&1)*2 + dir)*B_*H_;
    float* hnext       = hst + (size_t)(((t+1)&1)*2 + dir)*B_*H_;
    float acc[4][4] = {};
    float4 ph = *(const float4*)&hprev[(size_t)(b0+lr)*H_ + kg*4];
    float4 pw = *(const float4*)&Whh[(size_t)wrow*H_ + kg*4];
    for (int kc = 0; kc < H_; kc += 16){
      hs[kg*4+0][lr]=ph.x; hs[kg*4+1][lr]=ph.y; hs[kg*4+2][lr]=ph.z; hs[kg*4+3][lr]=ph.w;
      ws[kg*4+0][lr]=pw.x; ws[kg*4+1][lr]=pw.y; ws[kg*4+2][lr]=pw.z; ws[kg*4+3][lr]=pw.w;
      __syncthreads();
      if (kc + 16 < H_){
        ph = *(const float4*)&hprev[(size_t)(b0+lr)*H_ + kc+16 + kg*4];
        pw = *(const float4*)&Whh[(size_t)wrow*H_ + kc+16 + kg*4];
      }
      #pragma unroll
      for (int kk = 0; kk < 16; kk++){
        float4 a  = *(const float4*)&hs[kk][ty*4];
        float4 bv = *(const float4*)&ws[kk][tx*4];
        OUTER4(a, bv);
      }
      __syncthreads();
    }
    const int teff = dir ? (T_-1-t) : t;
    const int j = j0 + tx;
    #pragma unroll
    for (int i = 0; i < 4; i++){
      int bb = b0 + ty*4 + i;
      const float* xg = Xg + (size_t)(teff*B_ + bb)*1024;
      float gi = acc[i][0] + xg[j];
      float gf = acc[i][1] + xg[H_ + j];
      float gc = acc[i][2] + xg[2*H_ + j];
      float go = acc[i][3] + xg[3*H_ + j];
      size_t ci = (size_t)dir*B_*H_ + (size_t)bb*H_ + j;
      float c = cst[ci];
      c = sigm(gf)*c + sigm(gi)*ftanh(gc);
      float hv = sigm(go)*ftanh(c);
      cst[ci] = c;
      hnext[(size_t)bb*H_ + j] = hv;
      hout[(size_t)(teff*B_ + bb)*ENC_ + dir*H_ + j] = hv;
    }
    gbar(&g_bcL[dir], 32);
  }
}

__global__ void k_wcomb(const float* __restrict__ wih, const float* __restrict__ whh,
                        float* __restrict__ wc){
  size_t i = (size_t)blockIdx.x*256 + threadIdx.x, s = (size_t)gridDim.x*256;
  for (; i < (size_t)4096*KZ_; i += s){
    int n = (int)(i / KZ_), k = (int)(i - (size_t)n*KZ_);
    wc[i] = (k < 768) ? wih[(size_t)n*768 + k] : whh[(size_t)n*1024 + (k-768)];
  }
}
__global__ void k_wl2(const float* __restrict__ wl, float* __restrict__ w2){
  int i = blockIdx.x*256 + threadIdx.x;
  if (i < A_*31){ int a = i/31, k = i - a*31; w2[i] = wl[a*62 + k] + wl[a*62 + 31 + k]; }
}

// ---------------- persistent decoder ----------
__global__ void k_decoder(const float* __restrict__ mels,
                          const float* __restrict__ W1T, const float* __restrict__ pb1,
                          const float* __restrict__ W2T, const float* __restrict__ pb2,
                          const float* __restrict__ WqT, const float* __restrict__ pm,
                          const float* __restrict__ wl2, const float* __restrict__ av,
                          const float* __restrict__ mem, const float* __restrict__ Wc,
                          const float* __restrict__ db,  const float* __restrict__ oWT,
                          const float* __restrict__ ob,  float* __restrict__ out,
                          float* __restrict__ zin, float* __restrict__ hd,
                          float* __restrict__ cd, float* __restrict__ gates){
  __shared__ __align__(16) float sh[9936];
  const int tid = threadIdx.x;
  const int blk = blockIdx.x;
  const int b = blk;
  float* s_cum = sh + 9536;

  float wl[31]; float va_r;
  {
    int a = tid & 127;
    #pragma unroll
    for (int k = 0; k < 31; k++) wl[k] = wl2[a*31 + k];
    va_r = av[a];
  }

  for (int i = tid; i < T_; i += 256) s_cum[i] = 0.f;
  for (int i = tid; i < DEC_; i += 256){
    hd[(size_t)b*DEC_+i] = 0.f;
    cd[(size_t)b*DEC_+i] = 0.f;
    cd[(size_t)(B_+b)*DEC_+i] = 0.f;
  }
  gbar(&g_bc128, 128);

  for (int t = 0; t < T_; t++){
    const float* cdo = cd + (size_t)(t&1)*B_*DEC_;
    float*       cdn = cd + (size_t)((t+1)&1)*B_*DEC_;

    // ===== P123 =====
    {
      float* s_hd  = sh + 4414;
      float* s_din = sh + 5438;
      float* s_s1  = sh + 5520;
      float* s_pq  = sh + 9296;
      for (int i = tid; i < DEC_; i += 256){
        float v = hd[(size_t)b*DEC_ + i];
        s_hd[i] = v; zin[(size_t)b*KZ_ + 768 + i] = v;
      }
      if (tid < NM_) s_din[tid] = (t == 0) ? 0.f : mels[(size_t)(b*NM_ + tid)*T_ + (t-1)];
      __syncthreads();
      // warps 0-3: pq ; warps 4-7: prenet fc1 -> (bar 1) -> fc2
      if (tid < 128){
        float acc = 0.f;
        #pragma unroll 16
        for (int k = 0; k < DEC_; k++) acc += WqT[k*128 + tid]*s_hd[k];
        s_pq[tid] = acc;
      } else {
        int t2 = tid - 128;
        float a1a = pb1[t2], a1b = pb1[t2+128];
        #pragma unroll 8
        for (int m = 0; m < NM_; m++){
          float d = s_din[m];
          a1a += d*W1T[m*256 + t2];
          a1b += d*W1T[m*256 + t2 + 128];
        }
        s_s1[t2] = fmaxf(a1a, 0.f);
        s_s1[t2+128] = fmaxf(a1b, 0.f);
        asm volatile("bar.sync 1, 128;" ::: "memory");
        float a2a = pb2[t2], a2b = pb2[t2+128];
        #pragma unroll 16
        for (int k = 0; k < 256; k++){
          float s = s_s1[k];
          a2a += s*W2T[k*256 + t2];
          a2b += s*W2T[k*256 + t2 + 128];
        }
        zin[(size_t)b*KZ_ + t2] = fmaxf(a2a, 0.f);
        zin[(size_t)b*KZ_ + t2 + 128] = fmaxf(a2b, 0.f);
      }
      __syncthreads();

      // energy
      float* s_c  = sh + 3968;
      float* s_sv = sh + 4414;
      float* s_sp = sh + 8638;
      float* s_e  = sh + 8894;
      for (int i = tid; i < 446; i += 256){
        int tt = i - 15;
        s_c[i] = (tt >= 0 && tt < T_) ? s_cum[tt] : 0.f;
      }
      __syncthreads();
      const int sub = tid >> 7, a = tid & 127;
      const float pqa = s_pq[a];
      for (int it = 0; it < 13; it++){
        int chunk = it*2 + sub;
        if (chunk < 25){
          int t0 = chunk*16;
          #pragma unroll
          for (int j = 0; j < 16; j++){
            float pl = 0.f;
            #pragma unroll
            for (int k = 0; k < 31; k++) pl += wl[k]*s_c[t0 + j + k];
            float x = pqa + pm[(size_t)((t0+j)*B_ + b)*A_ + a] + pl;
            s_sv[(sub*16 + j)*132 + a] = va_r * ftanh(x);
          }
        }
        __syncthreads();
        {
          int r = tid >> 3, l = tid & 7;
          int chr = it*2 + (r >> 4);
          if (chr < 25){
            float p = 0.f;
            #pragma unroll
            for (int k = 0; k < 16; k++) p += s_sv[r*132 + l*16 + k];
            s_sp[r*8 + l] = p;
          }
        }
        __syncthreads();
        if (tid < 32){
          int chr = it*2 + (tid >> 4), jr = tid & 15;
          if (chr < 25){
            float s = 0.f;
            #pragma unroll
            for (int q = 0; q < 8; q++) s += s_sp[tid*8 + q];
            s_e[chr*16 + jr] = s;
          }
        }
        __syncthreads();
      }

      // softmax + cum + context
      float* s_al  = sh;
      float* s_red = sh + 5326;
      float v0 = s_e[tid];
      float v1 = (tid + 256 < T_) ? s_e[tid + 256] : -1e30f;
      s_red[tid] = fmaxf(v0, v1); __syncthreads();
      for (int s = 128; s; s >>= 1){ if (tid < s) s_red[tid] = fmaxf(s_red[tid], s_red[tid+s]); __syncthreads(); }
      float mx = s_red[0]; __syncthreads();
      float e0 = __expf(v0 - mx);
      float e1 = (tid + 256 < T_) ? __expf(v1 - mx) : 0.f;
      s_red[tid] = e0 + e1; __syncthreads();
      for (int s = 128; s; s >>= 1){ if (tid < s) s_red[tid] += s_red[tid+s]; __syncthreads(); }
      float inv = 1.f/s_red[0];
      float a0 = e0*inv;
      s_al[tid] = a0; s_cum[tid] += a0;
      if (tid + 256 < T_){
        float a1v = e1*inv;
        s_al[tid+256] = a1v; s_cum[tid+256] += a1v;
      }
      __syncthreads();
      float c0 = 0.f, c1 = 0.f;
      const float2* memb = (const float2*)(mem) + (size_t)b*256 + tid;
      #pragma unroll 8
      for (int tt = 0; tt < T_; tt++){
        float aw = s_al[tt];
        float2 m2 = memb[(size_t)tt*B_*256];
        c0 += aw*m2.x; c1 += aw*m2.y;
      }
      float2 cv; cv.x = c0; cv.y = c1;
      *(float2*)&zin[(size_t)b*KZ_ + 256 + 2*tid] = cv;
    }
    gbar(&g_bc128, 128);

    // ===== P4: cell GEMM 128x4096 @ K=1792 =====
    {
      const int m0 = (blk & 1)*64, n0 = (blk >> 1)*64;
      const int tx = tid&15, ty = tid>>4;
      float* As = sh;
      float* Ws = sh + 1024;
      ull ac2[4][2];
      #pragma unroll
      for (int i=0;i<4;i++){ ac2[i][0]=0ull; ac2[i][1]=0ull; }
      const int lr = tid & 63, kg = tid >> 6;
      const float* Arow = zin + (size_t)(m0+lr)*KZ_ + kg*4;
      const float* Wrow = Wc  + (size_t)(n0+lr)*KZ_ + kg*4;
      float4 pa0 = *(const float4*)(Arow);
      float4 pw0 = *(const float4*)(Wrow);
      float4 pa1 = *(const float4*)(Arow + 16);
      float4 pw1 = *(const float4*)(Wrow + 16);
      for (int kc = 0; kc < KZ_; kc += 16){
        As[(kg*4+0)*64+lr]=pa0.x; As[(kg*4+1)*64+lr]=pa0.y; As[(kg*4+2)*64+lr]=pa0.z; As[(kg*4+3)*64+lr]=pa0.w;
        Ws[(kg*4+0)*64+lr]=pw0.x; Ws[(kg*4+1)*64+lr]=pw0.y; Ws[(kg*4+2)*64+lr]=pw0.z; Ws[(kg*4+3)*64+lr]=pw0.w;
        __syncthreads();
        pa0 = pa1; pw0 = pw1;
        if (kc + 32 < KZ_){
          pa1 = *(const float4*)(Arow + kc + 32);
          pw1 = *(const float4*)(Wrow + kc + 32);
        }
        #pragma unroll
        for (int kk = 0; kk < 16; kk++){
          ulonglong2 am = *(const ulonglong2*)&As[kk*64 + ty*4];
          float4 bv = *(const float4*)&Ws[kk*64 + tx*4];
          POUTER4G(ac2, am, bv);
        }
        __syncthreads();
      }
      float bb[4] = {db[n0+tx*4+0], db[n0+tx*4+1], db[n0+tx*4+2], db[n0+tx*4+3]};
      float r[4][4];
      #pragma unroll
      for (int j = 0; j < 4; j++){
        unp2(r[0][j], r[1][j], ac2[j][0]);
        unp2(r[2][j], r[3][j], ac2[j][1]);
      }
      #pragma unroll
      for (int i = 0; i < 4; i++){
        float4 v; v.x=r[i][0]+bb[0]; v.y=r[i][1]+bb[1]; v.z=r[i][2]+bb[2]; v.w=r[i][3]+bb[3];
        *(float4*)&gates[(size_t)(m0+ty*4+i)*4096 + n0 + tx*4] = v;
      }
    }
    gbar(&g_bc128, 128);

    // ===== P56: cell update + output projection (64 blocks, n split) =====
    {
      int j = tid*4;
      float4 gi = *(const float4*)&gates[(size_t)b*4096 + j];
      float4 gf = *(const float4*)&gates[(size_t)b*4096 + 1024 + j];
      float4 gc = *(const float4*)&gates[(size_t)b*4096 + 2048 + j];
      float4 go = *(const float4*)&gates[(size_t)b*4096 + 3072 + j];
      float4 c  = *(const float4*)&cdo[(size_t)b*DEC_ + j];
      float4 hn;
      c.x = sigm(gf.x)*c.x + sigm(gi.x)*ftanh(gc.x); hn.x = sigm(go.x)*ftanh(c.x);
      c.y = sigm(gf.y)*c.y + sigm(gi.y)*ftanh(gc.y); hn.y = sigm(go.y)*ftanh(c.y);
      c.z = sigm(gf.z)*c.z + sigm(gi.z)*ftanh(gc.z); hn.z = sigm(go.z)*ftanh(c.z);
      c.w = sigm(gf.w)*c.w + sigm(gi.w)*ftanh(gc.w); hn.w = sigm(go.w)*ftanh(c.w);
      *(float4*)&cdn[(size_t)b*DEC_ + j] = c;
      *(float4*)&hd[(size_t)b*DEC_ + j] = hn;

      if (blk < 64){
        const int grp = blk & 31, half = blk >> 5;
        float* z = sh;  // [4][1544]
        #pragma unroll
        for (int bi = 0; bi < 4; bi++){
          int b2 = grp*4 + bi;
          float4 gi2 = *(const float4*)&gates[(size_t)b2*4096 + j];
          float4 gf2 = *(const float4*)&gates[(size_t)b2*4096 + 1024 + j];
          float4 gc2 = *(const float4*)&gates[(size_t)b2*4096 + 2048 + j];
          float4 go2 = *(const float4*)&gates[(size_t)b2*4096 + 3072 + j];
          float4 c2  = *(const float4*)&cdo[(size_t)b2*DEC_ + j];
          float4 h2;
          c2.x = sigm(gf2.x)*c2.x + sigm(gi2.x)*ftanh(gc2.x); h2.x = sigm(go2.x)*ftanh(c2.x);
          c2.y = sigm(gf2.y)*c2.y + sigm(gi2.y)*ftanh(gc2.y); h2.y = sigm(go2.y)*ftanh(c2.y);
          c2.z = sigm(gf2.z)*c2.z + sigm(gi2.z)*ftanh(gc2.z); h2.z = sigm(go2.z)*ftanh(c2.z);
          c2.w = sigm(gf2.w)*c2.w + sigm(gi2.w)*ftanh(gc2.w); h2.w = sigm(go2.w)*ftanh(c2.w);
          z[bi*1544 + j+0] = h2.x; z[bi*1544 + j+1] = h2.y;
          z[bi*1544 + j+2] = h2.z; z[bi*1544 + j+3] = h2.w;
        }
        for (int i = tid; i < 4*512; i += 256){
          int bi = i >> 9, kk = i & 511;
          z[bi*1544 + 1024 + kk] = zin[(size_t)(grp*4+bi)*KZ_ + 256 + kk];
        }
        __syncthreads();
        if (tid < 120){
          int n = half*120 + tid;
          float a0=0.f, a1=0.f, a2o=0.f, a3=0.f;
          #pragma unroll 16
          for (int k = 0; k < 1536; k++){
            float wv = oWT[k*240 + n];
            a0 += wv*z[0*1544+k]; a1 += wv*z[1*1544+k];
            a2o += wv*z[2*1544+k]; a3 += wv*z[3*1544+k];
          }
          float bb = ob[n];
          int r = n / NM_, m = n - r*NM_;
          float accv[4] = {a0+bb, a1+bb, a2o+bb, a3+bb};
          for (int bi = 0; bi < 4; bi++){
            int b2 = grp*4 + bi;
            float val = accv[bi];
            out[(size_t)b2*NM_*T3_ + (size_t)m*T3_ + 3*t + r] = val;
            if (m == NM_-1)
              out[(size_t)2*B_*NM_*T3_ + (size_t)b2*T3_ + 3*t + r] = sigm(val);
          }
        }
      }
      __syncthreads();  // order hd/cd writes before next step's strided reads
    }
  }
}

// ---------------- postnet conv1: writes channel-major p[o][b*T3+t] ------
__global__ void k_conv_post1(const float* __restrict__ mel, const float* __restrict__ w,
                             const float* __restrict__ bias, float* __restrict__ outp){
  const int col0 = blockIdx.x*64, o0 = blockIdx.y*64;
  const int tid = threadIdx.x, tx = tid&15, ty = tid>>4;
  __shared__ __align__(16) float As[16][64];
  __shared__ __align__(16) float Bs[16][64];
  float acc[4][4] = {};
  const int lr = tid & 63, kg = tid >> 6;
  for (int kc = 0; kc < NM_*5; kc += 16){
    float4 a4 = *(const float4*)&w[(size_t)(o0+lr)*(NM_*5) + kc + kg*4];
    As[kg*4+0][lr]=a4.x; As[kg*4+1][lr]=a4.y; As[kg*4+2][lr]=a4.z; As[kg*4+3][lr]=a4.w;
    #pragma unroll
    for (int q = 0; q < 4; q++){
      int e = tid + q*256, r = e>>6, cl = e&63;
      int rg = kc + r, m = rg/5, k = rg - m*5;
      int col = col0 + cl, b = col/T3_, t = col - b*T3_;
      int tp = t + k - 2;
      Bs[r][cl] = (tp >= 0 && tp < T3_) ? mel[(size_t)b*NM_*T3_ + (size_t)m*T3_ + tp] : 0.f;
    }
    __syncthreads();
    #pragma unroll
    for (int kk = 0; kk < 16; kk++){
      float4 a  = *(const float4*)&As[kk][ty*4];
      float4 bv = *(const float4*)&Bs[kk][tx*4];
      OUTER4(a, bv);
    }
    __syncthreads();
  }
  #pragma unroll
  for (int i = 0; i < 4; i++){
    int o = o0 + ty*4 + i;
    float bv = bias[o];
    #pragma unroll
    for (int j = 0; j < 4; j++){
      int col = col0 + tx*4 + j;
      outp[(size_t)o*BT3 + col] = acc[i][j] + bv;
    }
  }
}

// ---------------- postnet conv2 + residual (reads channel-major q) ------
__global__ void k_conv_post2(const float* __restrict__ q, const float* __restrict__ w2,
                             const float* __restrict__ bias, float* __restrict__ outp){
  const int col0 = blockIdx.x*64, m0 = blockIdx.y*64;
  const int tid = threadIdx.x, tx = tid&15, ty = tid>>4;
  __shared__ __align__(16) float As[16][64];
  __shared__ __align__(16) float Bs[16][64];
  float acc[4][4] = {};
  const int lr = tid & 63, kg = tid >> 6;
  const int row = m0 + lr;
  for (int kc = 0; kc < 2560; kc += 16){
    float4 a4 = make_float4(0.f,0.f,0.f,0.f);
    if (row < NM_) a4 = *(const float4*)&w2[(size_t)row*2560 + kc + kg*4];
    As[kg*4+0][lr]=a4.x; As[kg*4+1][lr]=a4.y; As[kg*4+2][lr]=a4.z; As[kg*4+3][lr]=a4.w;
    #pragma unroll
    for (int qq = 0; qq < 4; qq++){
      int e = tid + qq*256, r = e>>6, cl = e&63;
      int rg = kc + r, o = rg/5, k = rg - o*5;
      int col = col0 + cl, b = col/T3_, t = col - b*T3_;
      int tp = t + k - 2;
      Bs[r][cl] = (tp >= 0 && tp < T3_) ? q[(size_t)o*BT3 + b*T3_ + tp] : 0.f;
    }
    __syncthreads();
    #pragma unroll
    for (int kk = 0; kk < 16; kk++){
      float4 a  = *(const float4*)&As[kk][ty*4];
      float4 bv = *(const float4*)&Bs[kk][tx*4];
      OUTER4(a, bv);
    }
    __syncthreads();
  }
  const size_t OFF = (size_t)B_*NM_*T3_;
  #pragma unroll
  for (int i = 0; i < 4; i++){
    int m = m0 + ty*4 + i;
    if (m >= NM_) continue;
    float bb = bias[m];
    #pragma unroll
    for (int j = 0; j < 4; j++){
      int col = col0 + tx*4 + j, b = col/T3_, t = col - b*T3_;
      size_t midx = (size_t)b*NM_*T3_ + (size_t)m*T3_ + t;
      outp[OFF + midx] = acc[i][j] + bb + outp[midx];
    }
  }
}

// ======================= host launcher =======================
extern "C" void kernel_launch(void* const* d_in, const int* in_sizes, int n_in,
                              void* d_out, int out_size){
  const int*   text = (const int*)  d_in[0];
  const float* mels = (const float*)d_in[1];
  const float* emb  = (const float*)d_in[2];
  const float* ecw  = (const float*)d_in[3];
  const float* ecb  = (const float*)d_in[4];
  const float* bng  = (const float*)d_in[5];
  const float* bnb  = (const float*)d_in[6];
  const float* Wih  = (const float*)d_in[7];
  const float* Whh  = (const float*)d_in[8];
  const float* lb   = (const float*)d_in[9];
  const float* pW1  = (const float*)d_in[10];
  const float* pb1  = (const float*)d_in[11];
  const float* pW2  = (const float*)d_in[12];
  const float* pb2  = (const float*)d_in[13];
  const float* Wq   = (const float*)d_in[14];
  const float* Wm   = (const float*)d_in[15];
  const float* Wloc = (const float*)d_in[16];
  const float* av   = (const float*)d_in[17];
  const float* dWih = (const float*)d_in[18];
  const float* dWhh = (const float*)d_in[19];
  const float* db   = (const float*)d_in[20];
  const float* oW   = (const float*)d_in[21];
  const float* ob   = (const float*)d_in[22];
  const float* pw1  = (const float*)d_in[23];
  const float* pbb1 = (const float*)d_in[24];
  const float* pg   = (const float*)d_in[25];
  const float* pbt  = (const float*)d_in[26];
  const float* pw2  = (const float*)d_in[27];
  const float* pbb2 = (const float*)d_in[28];
  float* out = (float*)d_out;

  float *h0,*hB,*Xf,*Xb,*hst,*cst,*mean,*istd,*pm,*zin,*hd,*cd,*Wc,*wl2,*post;
  float *WqT,*W1T,*W2T,*oWT;
  cudaGetSymbolAddress((void**)&h0,  g_h0);
  cudaGetSymbolAddress((void**)&hB,  g_hB);
  cudaGetSymbolAddress((void**)&Xf,  g_Xf);
  cudaGetSymbolAddress((void**)&Xb,  g_Xb);
  cudaGetSymbolAddress((void**)&hst, g_hst);
  cudaGetSymbolAddress((void**)&cst, g_cst);
  cudaGetSymbolAddress((void**)&mean,g_mean);
  cudaGetSymbolAddress((void**)&istd,g_istd);
  cudaGetSymbolAddress((void**)&pm,  g_pm);
  cudaGetSymbolAddress((void**)&zin, g_zin);
  cudaGetSymbolAddress((void**)&hd,  g_hd);
  cudaGetSymbolAddress((void**)&cd,  g_cd);
  cudaGetSymbolAddress((void**)&Wc,  g_Wc);
  cudaGetSymbolAddress((void**)&wl2, g_wl2);
  cudaGetSymbolAddress((void**)&post,g_post);
  cudaGetSymbolAddress((void**)&WqT, g_WqT);
  cudaGetSymbolAddress((void**)&W1T, g_W1T);
  cudaGetSymbolAddress((void**)&W2T, g_W2T);
  cudaGetSymbolAddress((void**)&oWT, g_oWT);

  // ---- encoder ----
  k_conv_enc<<<dim3(B_*T_/64, ENC_/64), 256>>>(text, emb, ecw, ecb, h0);
  k_bn_stats<<<512, 256>>>(h0, mean, istd, T_*B_);
  k_bn_norm<<<4096, 256>>>(h0, mean, istd, bng, bnb, (size_t)T_*B_*512);

  float* hin = h0; float* hout = hB;
  for (int l = 0; l < 3; l++){
    k_sgemm_dual<<<dim3(T_*B_/64, 16), 256>>>(hin,
        Wih + (size_t)(l*2+0)*1024*512, lb + (l*2+0)*1024, Xf,
        Wih + (size_t)(l*2+1)*1024*512, lb + (l*2+1)*1024, Xb);
    k_lstm_layer<<<dim3(16, 2, 2), 256>>>(Xf, Xb, Whh + (size_t)l*2*1024*256,
                                          hst, cst, hout);
    float* tmp = hin; hin = hout; hout = tmp;
  }
  k_sgemm<<<dim3(T_*B_/64, 2), 256>>>(hin, Wm, (const float*)0, pm, T_*B_, A_, 512);

  // ---- decoder prep ----
  k_wcomb<<<8192, 256>>>(dWih, dWhh, Wc);
  k_wl2<<<16, 256>>>(Wloc, wl2);
  k_transp<<<(128*1024+255)/256, 256>>>(Wq,  WqT, 128, 1024);
  k_transp<<<(256*80 +255)/256, 256>>>(pW1, W1T, 256, 80);
  k_transp<<<(256*256+255)/256, 256>>>(pW2, W2T, 256, 256);
  k_transp<<<(240*1536+255)/256, 256>>>(oW, oWT, 240, 1536);

  // ---- decoder (single persistent launch) ----
  k_decoder<<<128, 256>>>(mels, W1T, pb1, W2T, pb2, WqT, pm, wl2, av,
                          hin, Wc, db, oWT, ob, out,
                          zin, hd, cd, Xf);

  // ---- postnet (channel-major intermediate) ----
  k_conv_post1<<<dim3(BT3/64, 8), 256>>>(out, pw1, pbb1, post);
  k_bn_stats_cm<<<512, 256>>>(post, mean, istd);
  k_bn_norm_cm<<<dim3((BT3+255)/256, 512), 256>>>(post, mean, istd, pg, pbt);
  k_conv_post2<<<dim3(BT3/64, 2), 256>>>(post, pw2, pbb2, out);
}

// round 15
// speedup vs baseline: 1.0605x; 1.0605x over previous
#include <cuda_runtime.h>
#include <math.h>

#define B_   128
#define T_   400
#define E_   512
#define ENC_ 512
#define DEC_ 1024
#define NM_  80
#define A_   128
#define H_   256
#define T3_  1200
#define KZ_  1792
#define BT3  (B_*T3_)

typedef unsigned long long ull;

__device__ __align__(16) float g_h0 [T_*B_*ENC_];
__device__ __align__(16) float g_hB [T_*B_*ENC_];
__device__ __align__(16) float g_Xf [T_*B_*1024];
__device__ __align__(16) float g_Xb [T_*B_*1024];
__device__ __align__(16) float g_hst[2*2*B_*H_];
__device__ __align__(16) float g_cst[2*B_*H_];
__device__ float g_mean[512], g_istd[512];
__device__ __align__(16) float g_pm [T_*B_*A_];
__device__ __align__(16) float g_zin[B_*KZ_];
__device__ __align__(16) float g_hd [B_*DEC_];
__device__ __align__(16) float g_cd [2*B_*DEC_];
__device__ __align__(16) float g_Wc [4096*KZ_];
__device__ float g_wl2[A_*31];
__device__ __align__(16) float g_post[(size_t)512*BT3];
__device__ __align__(16) float g_WqT[1024*128];
__device__ __align__(16) float g_W1T[80*256];
__device__ __align__(16) float g_W2T[256*256];
__device__ __align__(16) float g_oWT[1536*240];

__device__ unsigned long long g_bc64  = 0ull;
__device__ unsigned long long g_bc128 = 0ull;

__device__ __forceinline__ float sigm(float x){ return 1.f/(1.f+__expf(-x)); }
__device__ __forceinline__ float ftanh(float x){ float e = __expf(2.f*x); return 1.f - 2.f/(e+1.f); }

__device__ __forceinline__ ull pack2(float x){
  ull r; unsigned u = __float_as_uint(x);
  asm("mov.b64 %0, {%1, %1};" : "=l"(r) : "r"(u));
  return r;
}
__device__ __forceinline__ void fma2(ull& d, ull a, ull b){
  asm("fma.rn.f32x2 %0, %1, %2, %0;" : "+l"(d) : "l"(a), "l"(b));
}
__device__ __forceinline__ void unp2(float& lo, float& hi, ull v){
  unsigned a, b;
  asm("mov.b64 {%0, %1}, %2;" : "=r"(a), "=r"(b) : "l"(v));
  lo = __uint_as_float(a); hi = __uint_as_float(b);
}

__device__ __forceinline__ void gbar(unsigned long long* cnt, unsigned nb){
  __syncthreads();
  if (threadIdx.x == 0){
    __threadfence();
    unsigned long long my = atomicAdd(cnt, 1ull) + 1ull;
    unsigned long long target = ((my + nb - 1ull)/nb)*nb;
    while (*(volatile unsigned long long*)cnt < target) { }
    __threadfence();
  }
  __syncthreads();
}

#define OUTER4(a, bv) \
  acc[0][0]+=a.x*bv.x; acc[0][1]+=a.x*bv.y; acc[0][2]+=a.x*bv.z; acc[0][3]+=a.x*bv.w; \
  acc[1][0]+=a.y*bv.x; acc[1][1]+=a.y*bv.y; acc[1][2]+=a.y*bv.z; acc[1][3]+=a.y*bv.w; \
  acc[2][0]+=a.z*bv.x; acc[2][1]+=a.z*bv.y; acc[2][2]+=a.z*bv.z; acc[2][3]+=a.z*bv.w; \
  acc[3][0]+=a.w*bv.x; acc[3][1]+=a.w*bv.y; acc[3][2]+=a.w*bv.z; acc[3][3]+=a.w*bv.w;

#define POUTER4G(ac, am, bv) { \
  ull b0p=pack2(bv.x), b1p=pack2(bv.y), b2p=pack2(bv.z), b3p=pack2(bv.w); \
  fma2(ac[0][0], am.x, b0p); fma2(ac[0][1], am.y, b0p); \
  fma2(ac[1][0], am.x, b1p); fma2(ac[1][1], am.y, b1p); \
  fma2(ac[2][0], am.x, b2p); fma2(ac[2][1], am.y, b2p); \
  fma2(ac[3][0], am.x, b3p); fma2(ac[3][1], am.y, b3p); }

__global__ void k_transp(const float* __restrict__ s, float* __restrict__ d, int R, int C){
  int i = blockIdx.x*256 + threadIdx.x;
  if (i < R*C){ int r = i/C, c = i - r*C; d[c*R + r] = s[i]; }
}

// ---------------- encoder conv ----------
__global__ void k_conv_enc(const int* __restrict__ text, const float* __restrict__ emb,
                           const float* __restrict__ w, const float* __restrict__ bias,
                           float* __restrict__ outp){
  const int col0 = blockIdx.x*64, o0 = blockIdx.y*64;
  const int tid = threadIdx.x, tx = tid&15, ty = tid>>4;
  __shared__ int stok[64][5];
  __shared__ __align__(16) float As[16][64];
  __shared__ __align__(16) float Bs[16][64];
  for (int i = tid; i < 320; i += 256){
    int cl = i/5, k = i - cl*5;
    int col = col0 + cl, b = col/T_, t = col - b*T_;
    int tp = t + k - 2;
    stok[cl][k] = (tp >= 0 && tp < T_) ? text[b*T_ + tp] : -1;
  }
  float acc[4][4] = {};
  const int lr = tid & 63, kg = tid >> 6;
  __syncthreads();
  for (int kc = 0; kc < E_*5; kc += 16){
    float4 a4 = *(const float4*)&w[(size_t)(o0+lr)*(E_*5) + kc + kg*4];
    As[kg*4+0][lr]=a4.x; As[kg*4+1][lr]=a4.y; As[kg*4+2][lr]=a4.z; As[kg*4+3][lr]=a4.w;
    #pragma unroll
    for (int q = 0; q < 4; q++){
      int e = tid + q*256, r = e>>6, cl = e&63;
      int rg = kc + r, ii = rg/5, k = rg - ii*5;
      int tok = stok[cl][k];
      Bs[r][cl] = (tok >= 0) ? emb[tok*E_ + ii] : 0.f;
    }
    __syncthreads();
    #pragma unroll
    for (int kk = 0; kk < 16; kk++){
      float4 a  = *(const float4*)&As[kk][ty*4];
      float4 bv = *(const float4*)&Bs[kk][tx*4];
      OUTER4(a, bv);
    }
    __syncthreads();
  }
  float b0v=bias[o0+ty*4+0], b1v=bias[o0+ty*4+1], b2v=bias[o0+ty*4+2], b3v=bias[o0+ty*4+3];
  #pragma unroll
  for (int j = 0; j < 4; j++){
    int col = col0 + tx*4 + j, b = col/T_, t = col - b*T_;
    float4 v;
    v.x = fmaxf(acc[0][j]+b0v, 0.f);
    v.y = fmaxf(acc[1][j]+b1v, 0.f);
    v.z = fmaxf(acc[2][j]+b2v, 0.f);
    v.w = fmaxf(acc[3][j]+b3v, 0.f);
    *(float4*)&outp[(size_t)(t*B_+b)*ENC_ + o0 + ty*4] = v;
  }
}

// ---------------- encoder BN (channel-last) ----------
__global__ void k_bn_stats(const float* __restrict__ x, float* mean, float* istd, int rows){
  int o = blockIdx.x, tid = threadIdx.x;
  float s = 0.f, ss = 0.f;
  for (int r = tid; r < rows; r += 256){
    float v = x[(size_t)r*512 + o]; s += v; ss += v*v;
  }
  __shared__ float rs[256], rq[256];
  rs[tid]=s; rq[tid]=ss; __syncthreads();
  for (int st = 128; st; st >>= 1){
    if (tid < st){ rs[tid]+=rs[tid+st]; rq[tid]+=rq[tid+st]; }
    __syncthreads();
  }
  if (tid == 0){
    float m = rs[0]/(float)rows;
    float var = rq[0]/(float)rows - m*m;
    mean[o] = m; istd[o] = rsqrtf(var + 1e-5f);
  }
}
__global__ void k_bn_norm(float* x, const float* mean, const float* istd,
                          const float* g, const float* bt, size_t n){
  size_t i = (size_t)blockIdx.x*256 + threadIdx.x, s = (size_t)gridDim.x*256;
  for (; i < n; i += s){
    int o = (int)(i & 511);
    x[i] = (x[i]-mean[o])*istd[o]*g[o] + bt[o];
  }
}

// ---------------- postnet BN (channel-major, coalesced) ----------
__global__ void k_bn_stats_cm(const float* __restrict__ x, float* mean, float* istd){
  int o = blockIdx.x, tid = threadIdx.x;
  const float* row = x + (size_t)o*BT3;
  float s = 0.f, ss = 0.f;
  for (int i = tid; i < BT3; i += 256){ float v = row[i]; s += v; ss += v*v; }
  __shared__ float rs[256], rq[256];
  rs[tid]=s; rq[tid]=ss; __syncthreads();
  for (int st = 128; st; st >>= 1){
    if (tid < st){ rs[tid]+=rs[tid+st]; rq[tid]+=rq[tid+st]; }
    __syncthreads();
  }
  if (tid == 0){
    float m = rs[0]/(float)BT3;
    float var = rq[0]/(float)BT3 - m*m;
    mean[o] = m; istd[o] = rsqrtf(var + 1e-5f);
  }
}
__global__ void k_bn_norm_cm(float* x, const float* mean, const float* istd,
                             const float* g, const float* bt){
  int o = blockIdx.y;
  int i = blockIdx.x*256 + threadIdx.x;
  if (i < BT3){
    size_t idx = (size_t)o*BT3 + i;
    float v = (x[idx]-mean[o])*istd[o]*g[o] + bt[o];
    x[idx] = ftanh(v);
  }
}

// ---------------- SGEMM (f32x2 packed): C[M,N] = A@W^T (+bias) ------
__global__ void k_sgemm(const float* __restrict__ Am, const float* __restrict__ Wm,
                        const float* __restrict__ bias, float* __restrict__ C,
                        int M, int N, int K){
  int m0 = blockIdx.x*64, n0 = blockIdx.y*64;
  int tid = threadIdx.x, tx = tid&15, ty = tid>>4;
  __shared__ __align__(16) float As[16][64];
  __shared__ __align__(16) float Ws[16][64];
  ull ac2[4][2];
  #pragma unroll
  for (int i=0;i<4;i++){ ac2[i][0]=0ull; ac2[i][1]=0ull; }
  int lr = tid & 63, kg = tid >> 6;
  float4 pa = *(const float4*)&Am[(size_t)(m0+lr)*K + kg*4];
  float4 pw = *(const float4*)&Wm[(size_t)(n0+lr)*K + kg*4];
  for (int kc = 0; kc < K; kc += 16){
    As[kg*4+0][lr]=pa.x; As[kg*4+1][lr]=pa.y; As[kg*4+2][lr]=pa.z; As[kg*4+3][lr]=pa.w;
    Ws[kg*4+0][lr]=pw.x; Ws[kg*4+1][lr]=pw.y; Ws[kg*4+2][lr]=pw.z; Ws[kg*4+3][lr]=pw.w;
    __syncthreads();
    if (kc + 16 < K){
      pa = *(const float4*)&Am[(size_t)(m0+lr)*K + kc+16 + kg*4];
      pw = *(const float4*)&Wm[(size_t)(n0+lr)*K + kc+16 + kg*4];
    }
    #pragma unroll
    for (int kk = 0; kk < 16; kk++){
      ulonglong2 am = *(const ulonglong2*)&As[kk][ty*4];
      float4 bv = *(const float4*)&Ws[kk][tx*4];
      POUTER4G(ac2, am, bv);
    }
    __syncthreads();
  }
  float bb[4] = {0,0,0,0};
  if (bias){ bb[0]=bias[n0+tx*4+0]; bb[1]=bias[n0+tx*4+1]; bb[2]=bias[n0+tx*4+2]; bb[3]=bias[n0+tx*4+3]; }
  float r[4][4];
  #pragma unroll
  for (int j = 0; j < 4; j++){
    unp2(r[0][j], r[1][j], ac2[j][0]);
    unp2(r[2][j], r[3][j], ac2[j][1]);
  }
  #pragma unroll
  for (int i = 0; i < 4; i++){
    float4 v; v.x=r[i][0]+bb[0]; v.y=r[i][1]+bb[1]; v.z=r[i][2]+bb[2]; v.w=r[i][3]+bb[3];
    *(float4*)&C[(size_t)(m0+ty*4+i)*N + n0 + tx*4] = v;
  }
}

// ---------------- dual SGEMM: shares A-tile for fwd+bwd LSTM input ------
__global__ void k_sgemm_dual(const float* __restrict__ Am,
                             const float* __restrict__ Wf, const float* __restrict__ bf, float* __restrict__ Cf,
                             const float* __restrict__ Wb, const float* __restrict__ bb_, float* __restrict__ Cb){
  const int K = 512, N = 1024;
  int m0 = blockIdx.x*64, n0 = blockIdx.y*64;
  int tid = threadIdx.x, tx = tid&15, ty = tid>>4;
  __shared__ __align__(16) float As[16*64];
  __shared__ __align__(16) float Wsf[16*64];
  __shared__ __align__(16) float Wsb[16*64];
  ull acf[4][2], acb[4][2];
  #pragma unroll
  for (int i=0;i<4;i++){ acf[i][0]=0; acf[i][1]=0; acb[i][0]=0; acb[i][1]=0; }
  int lr = tid & 63, kg = tid >> 6;
  float4 pa = *(const float4*)&Am[(size_t)(m0+lr)*K + kg*4];
  float4 pf = *(const float4*)&Wf[(size_t)(n0+lr)*K + kg*4];
  float4 pb = *(const float4*)&Wb[(size_t)(n0+lr)*K + kg*4];
  for (int kc = 0; kc < K; kc += 16){
    As [(kg*4+0)*64+lr]=pa.x; As [(kg*4+1)*64+lr]=pa.y; As [(kg*4+2)*64+lr]=pa.z; As [(kg*4+3)*64+lr]=pa.w;
    Wsf[(kg*4+0)*64+lr]=pf.x; Wsf[(kg*4+1)*64+lr]=pf.y; Wsf[(kg*4+2)*64+lr]=pf.z; Wsf[(kg*4+3)*64+lr]=pf.w;
    Wsb[(kg*4+0)*64+lr]=pb.x; Wsb[(kg*4+1)*64+lr]=pb.y; Wsb[(kg*4+2)*64+lr]=pb.z; Wsb[(kg*4+3)*64+lr]=pb.w;
    __syncthreads();
    if (kc + 16 < K){
      pa = *(const float4*)&Am[(size_t)(m0+lr)*K + kc+16 + kg*4];
      pf = *(const float4*)&Wf[(size_t)(n0+lr)*K + kc+16 + kg*4];
      pb = *(const float4*)&Wb[(size_t)(n0+lr)*K + kc+16 + kg*4];
    }
    #pragma unroll
    for (int kk = 0; kk < 16; kk++){
      ulonglong2 am = *(const ulonglong2*)&As[kk*64 + ty*4];
      float4 bvf = *(const float4*)&Wsf[kk*64 + tx*4];
      POUTER4G(acf, am, bvf);
      float4 bvb = *(const float4*)&Wsb[kk*64 + tx*4];
      POUTER4G(acb, am, bvb);
    }
    __syncthreads();
  }
  float bfv[4] = {bf[n0+tx*4+0], bf[n0+tx*4+1], bf[n0+tx*4+2], bf[n0+tx*4+3]};
  float bbv[4] = {bb_[n0+tx*4+0], bb_[n0+tx*4+1], bb_[n0+tx*4+2], bb_[n0+tx*4+3]};
  float rf[4][4], rb[4][4];
  #pragma unroll
  for (int j = 0; j < 4; j++){
    unp2(rf[0][j], rf[1][j], acf[j][0]); unp2(rf[2][j], rf[3][j], acf[j][1]);
    unp2(rb[0][j], rb[1][j], acb[j][0]); unp2(rb[2][j], rb[3][j], acb[j][1]);
  }
  #pragma unroll
  for (int i = 0; i < 4; i++){
    float4 v1; v1.x=rf[i][0]+bfv[0]; v1.y=rf[i][1]+bfv[1]; v1.z=rf[i][2]+bfv[2]; v1.w=rf[i][3]+bfv[3];
    *(float4*)&Cf[(size_t)(m0+ty*4+i)*N + n0 + tx*4] = v1;
    float4 v2; v2.x=rb[i][0]+bbv[0]; v2.y=rb[i][1]+bbv[1]; v2.z=rb[i][2]+bbv[2]; v2.w=rb[i][3]+bbv[3];
    *(float4*)&Cb[(size_t)(m0+ty*4+i)*N + n0 + tx*4] = v2;
  }
}

// ---------------- persistent biLSTM layer (R13 version) ----------
__global__ void k_lstm_layer(const float* __restrict__ Xf, const float* __restrict__ Xb,
                             const float* __restrict__ Whh_base,
                             float* __restrict__ hst, float* __restrict__ cst,
                             float* __restrict__ hout){
  const int jt = blockIdx.x, bt = blockIdx.y, dir = blockIdx.z;
  const int tid = threadIdx.x, tx = tid&15, ty = tid>>4;
  const int b0 = bt*64, j0 = jt*16;
  const float* Whh = Whh_base + (size_t)dir*4*H_*H_;
  const float* Xg  = dir ? Xb : Xf;
  __shared__ __align__(16) float hs[16][64];
  __shared__ __align__(16) float ws[16][64];
  const int lr = tid & 63, kg = tid >> 6;
  const int wrow = (lr&3)*H_ + j0 + (lr>>2);

  for (int i = tid; i < 64*16; i += 256){
    int bb = b0 + (i>>4), j = j0 + (i&15);
    hst[(size_t)(0*2+dir)*B_*H_ + bb*H_ + j] = 0.f;
    hst[(size_t)(1*2+dir)*B_*H_ + bb*H_ + j] = 0.f;
    cst[(size_t)dir*B_*H_ + bb*H_ + j] = 0.f;
  }
  gbar(&g_bc64, 64);

  for (int t = 0; t < T_; t++){
    const float* hprev = hst + (size_t)((t&1)*2 + dir)*B_*H_;
    float* hnext       = hst + (size_t)(((t+1)&1)*2 + dir)*B_*H_;
    float acc[4][4] = {};
    float4 ph = *(const float4*)&hprev[(size_t)(b0+lr)*H_ + kg*4];
    float4 pw = *(const float4*)&Whh[(size_t)wrow*H_ + kg*4];
    for (int kc = 0; kc < H_; kc += 16){
      hs[kg*4+0][lr]=ph.x; hs[kg*4+1][lr]=ph.y; hs[kg*4+2][lr]=ph.z; hs[kg*4+3][lr]=ph.w;
      ws[kg*4+0][lr]=pw.x; ws[kg*4+1][lr]=pw.y; ws[kg*4+2][lr]=pw.z; ws[kg*4+3][lr]=pw.w;
      __syncthreads();
      if (kc + 16 < H_){
        ph = *(const float4*)&hprev[(size_t)(b0+lr)*H_ + kc+16 + kg*4];
        pw = *(const float4*)&Whh[(size_t)wrow*H_ + kc+16 + kg*4];
      }
      #pragma unroll
      for (int kk = 0; kk < 16; kk++){
        float4 a  = *(const float4*)&hs[kk][ty*4];
        float4 bv = *(const float4*)&ws[kk][tx*4];
        OUTER4(a, bv);
      }
      __syncthreads();
    }
    const int teff = dir ? (T_-1-t) : t;
    const int j = j0 + tx;
    #pragma unroll
    for (int i = 0; i < 4; i++){
      int bb = b0 + ty*4 + i;
      const float* xg = Xg + (size_t)(teff*B_ + bb)*1024;
      float gi = acc[i][0] + xg[j];
      float gf = acc[i][1] + xg[H_ + j];
      float gc = acc[i][2] + xg[2*H_ + j];
      float go = acc[i][3] + xg[3*H_ + j];
      size_t ci = (size_t)dir*B_*H_ + (size_t)bb*H_ + j;
      float c = cst[ci];
      c = sigm(gf)*c + sigm(gi)*ftanh(gc);
      float hv = sigm(go)*ftanh(c);
      cst[ci] = c;
      hnext[(size_t)bb*H_ + j] = hv;
      hout[(size_t)(teff*B_ + bb)*ENC_ + dir*H_ + j] = hv;
    }
    gbar(&g_bc64, 64);
  }
}

__global__ void k_wcomb(const float* __restrict__ wih, const float* __restrict__ whh,
                        float* __restrict__ wc){
  size_t i = (size_t)blockIdx.x*256 + threadIdx.x, s = (size_t)gridDim.x*256;
  for (; i < (size_t)4096*KZ_; i += s){
    int n = (int)(i / KZ_), k = (int)(i - (size_t)n*KZ_);
    wc[i] = (k < 768) ? wih[(size_t)n*768 + k] : whh[(size_t)n*1024 + (k-768)];
  }
}
__global__ void k_wl2(const float* __restrict__ wl, float* __restrict__ w2){
  int i = blockIdx.x*256 + threadIdx.x;
  if (i < A_*31){ int a = i/31, k = i - a*31; w2[i] = wl[a*62 + k] + wl[a*62 + 31 + k]; }
}

// ---------------- persistent decoder (R13 version, verbatim) ----------
__global__ void k_decoder(const float* __restrict__ mels,
                          const float* __restrict__ W1T, const float* __restrict__ pb1,
                          const float* __restrict__ W2T, const float* __restrict__ pb2,
                          const float* __restrict__ WqT, const float* __restrict__ pm,
                          const float* __restrict__ wl2, const float* __restrict__ av,
                          const float* __restrict__ mem, const float* __restrict__ Wc,
                          const float* __restrict__ db,  const float* __restrict__ oWT,
                          const float* __restrict__ ob,  float* __restrict__ out,
                          float* __restrict__ zin, float* __restrict__ hd,
                          float* __restrict__ cd, float* __restrict__ gates){
  __shared__ __align__(16) float sh[9936];
  const int tid = threadIdx.x;
  const int blk = blockIdx.x;
  const int b = blk;
  float* s_cum = sh + 9536;

  float wl[31]; float va_r;
  {
    int a = tid & 127;
    #pragma unroll
    for (int k = 0; k < 31; k++) wl[k] = wl2[a*31 + k];
    va_r = av[a];
  }

  for (int i = tid; i < T_; i += 256) s_cum[i] = 0.f;
  for (int i = tid; i < DEC_; i += 256){
    hd[(size_t)b*DEC_+i] = 0.f;
    cd[(size_t)b*DEC_+i] = 0.f;
    cd[(size_t)(B_+b)*DEC_+i] = 0.f;
  }
  gbar(&g_bc128, 128);

  for (int t = 0; t < T_; t++){
    const float* cdo = cd + (size_t)(t&1)*B_*DEC_;
    float*       cdn = cd + (size_t)((t+1)&1)*B_*DEC_;

    // ===== P123 =====
    {
      float* s_hd  = sh + 4414;
      float* s_din = sh + 5438;
      float* s_s1  = sh + 5520;
      float* s_pq  = sh + 9296;
      for (int i = tid; i < DEC_; i += 256){
        float v = hd[(size_t)b*DEC_ + i];
        s_hd[i] = v; zin[(size_t)b*KZ_ + 768 + i] = v;
      }
      if (tid < NM_) s_din[tid] = (t == 0) ? 0.f : mels[(size_t)(b*NM_ + tid)*T_ + (t-1)];
      __syncthreads();
      float a1 = pb1[tid];
      #pragma unroll 8
      for (int m = 0; m < NM_; m++) a1 += s_din[m]*W1T[m*256 + tid];
      s_s1[tid] = fmaxf(a1, 0.f);
      __syncthreads();
      float a2 = pb2[tid];
      #pragma unroll 16
      for (int k = 0; k < 256; k++) a2 += s_s1[k]*W2T[k*256 + tid];
      zin[(size_t)b*KZ_ + tid] = fmaxf(a2, 0.f);
      if (tid < A_){
        float acc = 0.f;
        #pragma unroll 16
        for (int k = 0; k < DEC_; k++) acc += WqT[k*128 + tid]*s_hd[k];
        s_pq[tid] = acc;
      }
      __syncthreads();

      // energy
      float* s_c  = sh + 3968;
      float* s_sv = sh + 4414;
      float* s_sp = sh + 8638;
      float* s_e  = sh + 8894;
      for (int i = tid; i < 446; i += 256){
        int tt = i - 15;
        s_c[i] = (tt >= 0 && tt < T_) ? s_cum[tt] : 0.f;
      }
      __syncthreads();
      const int sub = tid >> 7, a = tid & 127;
      const float pqa = s_pq[a];
      for (int it = 0; it < 13; it++){
        int chunk = it*2 + sub;
        if (chunk < 25){
          int t0 = chunk*16;
          #pragma unroll
          for (int j = 0; j < 16; j++){
            float pl = 0.f;
            #pragma unroll
            for (int k = 0; k < 31; k++) pl += wl[k]*s_c[t0 + j + k];
            float x = pqa + pm[(size_t)((t0+j)*B_ + b)*A_ + a] + pl;
            s_sv[(sub*16 + j)*132 + a] = va_r * ftanh(x);
          }
        }
        __syncthreads();
        {
          int r = tid >> 3, l = tid & 7;
          int chr = it*2 + (r >> 4);
          if (chr < 25){
            float p = 0.f;
            #pragma unroll
            for (int k = 0; k < 16; k++) p += s_sv[r*132 + l*16 + k];
            s_sp[r*8 + l] = p;
          }
        }
        __syncthreads();
        if (tid < 32){
          int chr = it*2 + (tid >> 4), jr = tid & 15;
          if (chr < 25){
            float s = 0.f;
            #pragma unroll
            for (int q = 0; q < 8; q++) s += s_sp[tid*8 + q];
            s_e[chr*16 + jr] = s;
          }
        }
        __syncthreads();
      }

      // softmax + cum + context
      float* s_al  = sh;
      float* s_red = sh + 5326;
      float v0 = s_e[tid];
      float v1 = (tid + 256 < T_) ? s_e[tid + 256] : -1e30f;
      s_red[tid] = fmaxf(v0, v1); __syncthreads();
      for (int s = 128; s; s >>= 1){ if (tid < s) s_red[tid] = fmaxf(s_red[tid], s_red[tid+s]); __syncthreads(); }
      float mx = s_red[0]; __syncthreads();
      float e0 = __expf(v0 - mx);
      float e1 = (tid + 256 < T_) ? __expf(v1 - mx) : 0.f;
      s_red[tid] = e0 + e1; __syncthreads();
      for (int s = 128; s; s >>= 1){ if (tid < s) s_red[tid] += s_red[tid+s]; __syncthreads(); }
      float inv = 1.f/s_red[0];
      float a0 = e0*inv;
      s_al[tid] = a0; s_cum[tid] += a0;
      if (tid + 256 < T_){
        float a1v = e1*inv;
        s_al[tid+256] = a1v; s_cum[tid+256] += a1v;
      }
      __syncthreads();
      float c0 = 0.f, c1 = 0.f;
      const float2* memb = (const float2*)(mem) + (size_t)b*256 + tid;
      #pragma unroll 8
      for (int tt = 0; tt < T_; tt++){
        float aw = s_al[tt];
        float2 m2 = memb[(size_t)tt*B_*256];
        c0 += aw*m2.x; c1 += aw*m2.y;
      }
      float2 cv; cv.x = c0; cv.y = c1;
      *(float2*)&zin[(size_t)b*KZ_ + 256 + 2*tid] = cv;
    }
    gbar(&g_bc128, 128);

    // ===== P4: cell GEMM 128x4096 @ K=1792 =====
    {
      const int m0 = (blk & 1)*64, n0 = (blk >> 1)*64;
      const int tx = tid&15, ty = tid>>4;
      float* As = sh;
      float* Ws = sh + 1024;
      ull ac2[4][2];
      #pragma unroll
      for (int i=0;i<4;i++){ ac2[i][0]=0ull; ac2[i][1]=0ull; }
      const int lr = tid & 63, kg = tid >> 6;
      const float* Arow = zin + (size_t)(m0+lr)*KZ_ + kg*4;
      const float* Wrow = Wc  + (size_t)(n0+lr)*KZ_ + kg*4;
      float4 pa0 = *(const float4*)(Arow);
      float4 pw0 = *(const float4*)(Wrow);
      float4 pa1 = *(const float4*)(Arow + 16);
      float4 pw1 = *(const float4*)(Wrow + 16);
      for (int kc = 0; kc < KZ_; kc += 16){
        As[(kg*4+0)*64+lr]=pa0.x; As[(kg*4+1)*64+lr]=pa0.y; As[(kg*4+2)*64+lr]=pa0.z; As[(kg*4+3)*64+lr]=pa0.w;
        Ws[(kg*4+0)*64+lr]=pw0.x; Ws[(kg*4+1)*64+lr]=pw0.y; Ws[(kg*4+2)*64+lr]=pw0.z; Ws[(kg*4+3)*64+lr]=pw0.w;
        __syncthreads();
        pa0 = pa1; pw0 = pw1;
        if (kc + 32 < KZ_){
          pa1 = *(const float4*)(Arow + kc + 32);
          pw1 = *(const float4*)(Wrow + kc + 32);
        }
        #pragma unroll
        for (int kk = 0; kk < 16; kk++){
          ulonglong2 am = *(const ulonglong2*)&As[kk*64 + ty*4];
          float4 bv = *(const float4*)&Ws[kk*64 + tx*4];
          POUTER4G(ac2, am, bv);
        }
        __syncthreads();
      }
      float bb[4] = {db[n0+tx*4+0], db[n0+tx*4+1], db[n0+tx*4+2], db[n0+tx*4+3]};
      float r[4][4];
      #pragma unroll
      for (int j = 0; j < 4; j++){
        unp2(r[0][j], r[1][j], ac2[j][0]);
        unp2(r[2][j], r[3][j], ac2[j][1]);
      }
      #pragma unroll
      for (int i = 0; i < 4; i++){
        float4 v; v.x=r[i][0]+bb[0]; v.y=r[i][1]+bb[1]; v.z=r[i][2]+bb[2]; v.w=r[i][3]+bb[3];
        *(float4*)&gates[(size_t)(m0+ty*4+i)*4096 + n0 + tx*4] = v;
      }
    }
    gbar(&g_bc128, 128);

    // ===== P56: cell update + output projection =====
    {
      int j = tid*4;
      float4 gi = *(const float4*)&gates[(size_t)b*4096 + j];
      float4 gf = *(const float4*)&gates[(size_t)b*4096 + 1024 + j];
      float4 gc = *(const float4*)&gates[(size_t)b*4096 + 2048 + j];
      float4 go = *(const float4*)&gates[(size_t)b*4096 + 3072 + j];
      float4 c  = *(const float4*)&cdo[(size_t)b*DEC_ + j];
      float4 hn;
      c.x = sigm(gf.x)*c.x + sigm(gi.x)*ftanh(gc.x); hn.x = sigm(go.x)*ftanh(c.x);
      c.y = sigm(gf.y)*c.y + sigm(gi.y)*ftanh(gc.y); hn.y = sigm(go.y)*ftanh(c.y);
      c.z = sigm(gf.z)*c.z + sigm(gi.z)*ftanh(gc.z); hn.z = sigm(go.z)*ftanh(c.z);
      c.w = sigm(gf.w)*c.w + sigm(gi.w)*ftanh(gc.w); hn.w = sigm(go.w)*ftanh(c.w);
      *(float4*)&cdn[(size_t)b*DEC_ + j] = c;
      *(float4*)&hd[(size_t)b*DEC_ + j] = hn;

      if (blk < 32){
        float* z = sh;  // [4][1544]
        #pragma unroll
        for (int bi = 0; bi < 4; bi++){
          int b2 = blk*4 + bi;
          float4 gi2 = *(const float4*)&gates[(size_t)b2*4096 + j];
          float4 gf2 = *(const float4*)&gates[(size_t)b2*4096 + 1024 + j];
          float4 gc2 = *(const float4*)&gates[(size_t)b2*4096 + 2048 + j];
          float4 go2 = *(const float4*)&gates[(size_t)b2*4096 + 3072 + j];
          float4 c2  = *(const float4*)&cdo[(size_t)b2*DEC_ + j];
          float4 h2;
          c2.x = sigm(gf2.x)*c2.x + sigm(gi2.x)*ftanh(gc2.x); h2.x = sigm(go2.x)*ftanh(c2.x);
          c2.y = sigm(gf2.y)*c2.y + sigm(gi2.y)*ftanh(gc2.y); h2.y = sigm(go2.y)*ftanh(c2.y);
          c2.z = sigm(gf2.z)*c2.z + sigm(gi2.z)*ftanh(gc2.z); h2.z = sigm(go2.z)*ftanh(c2.z);
          c2.w = sigm(gf2.w)*c2.w + sigm(gi2.w)*ftanh(gc2.w); h2.w = sigm(go2.w)*ftanh(c2.w);
          z[bi*1544 + j+0] = h2.x; z[bi*1544 + j+1] = h2.y;
          z[bi*1544 + j+2] = h2.z; z[bi*1544 + j+3] = h2.w;
        }
        for (int i = tid; i < 4*512; i += 256){
          int bi = i >> 9, kk = i & 511;
          z[bi*1544 + 1024 + kk] = zin[(size_t)(blk*4+bi)*KZ_ + 256 + kk];
        }
        __syncthreads();
        int n = tid;
        if (n < 240){
          float a0=0.f, a1=0.f, a2o=0.f, a3=0.f;
          #pragma unroll 16
          for (int k = 0; k < 1536; k++){
            float wv = oWT[k*240 + n];
            a0 += wv*z[0*1544+k]; a1 += wv*z[1*1544+k];
            a2o += wv*z[2*1544+k]; a3 += wv*z[3*1544+k];
          }
          float bb = ob[n];
          int r = n / NM_, m = n - r*NM_;
          float accv[4] = {a0+bb, a1+bb, a2o+bb, a3+bb};
          for (int bi = 0; bi < 4; bi++){
            int b2 = blk*4 + bi;
            float val = accv[bi];
            out[(size_t)b2*NM_*T3_ + (size_t)m*T3_ + 3*t + r] = val;
            if (m == NM_-1)
              out[(size_t)2*B_*NM_*T3_ + (size_t)b2*T3_ + 3*t + r] = sigm(val);
          }
        }
      }
      __syncthreads();  // order hd/cd writes before next step's strided reads
    }
  }
}

// ---------------- postnet conv1: writes channel-major p[o][b*T3+t] ------
__global__ void k_conv_post1(const float* __restrict__ mel, const float* __restrict__ w,
                             const float* __restrict__ bias, float* __restrict__ outp){
  const int col0 = blockIdx.x*64, o0 = blockIdx.y*64;
  const int tid = threadIdx.x, tx = tid&15, ty = tid>>4;
  __shared__ __align__(16) float As[16][64];
  __shared__ __align__(16) float Bs[16][64];
  float acc[4][4] = {};
  const int lr = tid & 63, kg = tid >> 6;
  for (int kc = 0; kc < NM_*5; kc += 16){
    float4 a4 = *(const float4*)&w[(size_t)(o0+lr)*(NM_*5) + kc + kg*4];
    As[kg*4+0][lr]=a4.x; As[kg*4+1][lr]=a4.y; As[kg*4+2][lr]=a4.z; As[kg*4+3][lr]=a4.w;
    #pragma unroll
    for (int q = 0; q < 4; q++){
      int e = tid + q*256, r = e>>6, cl = e&63;
      int rg = kc + r, m = rg/5, k = rg - m*5;
      int col = col0 + cl, b = col/T3_, t = col - b*T3_;
      int tp = t + k - 2;
      Bs[r][cl] = (tp >= 0 && tp < T3_) ? mel[(size_t)b*NM_*T3_ + (size_t)m*T3_ + tp] : 0.f;
    }
    __syncthreads();
    #pragma unroll
    for (int kk = 0; kk < 16; kk++){
      float4 a  = *(const float4*)&As[kk][ty*4];
      float4 bv = *(const float4*)&Bs[kk][tx*4];
      OUTER4(a, bv);
    }
    __syncthreads();
  }
  #pragma unroll
  for (int i = 0; i < 4; i++){
    int o = o0 + ty*4 + i;
    float bv = bias[o];
    #pragma unroll
    for (int j = 0; j < 4; j++){
      int col = col0 + tx*4 + j;
      outp[(size_t)o*BT3 + col] = acc[i][j] + bv;
    }
  }
}

// ---------------- postnet conv2 + residual (reads channel-major q) ------
__global__ void k_conv_post2(const float* __restrict__ q, const float* __restrict__ w2,
                             const float* __restrict__ bias, float* __restrict__ outp){
  const int col0 = blockIdx.x*64, m0 = blockIdx.y*64;
  const int tid = threadIdx.x, tx = tid&15, ty = tid>>4;
  __shared__ __align__(16) float As[16][64];
  __shared__ __align__(16) float Bs[16][64];
  float acc[4][4] = {};
  const int lr = tid & 63, kg = tid >> 6;
  const int row = m0 + lr;
  for (int kc = 0; kc < 2560; kc += 16){
    float4 a4 = make_float4(0.f,0.f,0.f,0.f);
    if (row < NM_) a4 = *(const float4*)&w2[(size_t)row*2560 + kc + kg*4];
    As[kg*4+0][lr]=a4.x; As[kg*4+1][lr]=a4.y; As[kg*4+2][lr]=a4.z; As[kg*4+3][lr]=a4.w;
    #pragma unroll
    for (int qq = 0; qq < 4; qq++){
      int e = tid + qq*256, r = e>>6, cl = e&63;
      int rg = kc + r, o = rg/5, k = rg - o*5;
      int col = col0 + cl, b = col/T3_, t = col - b*T3_;
      int tp = t + k - 2;
      Bs[r][cl] = (tp >= 0 && tp < T3_) ? q[(size_t)o*BT3 + b*T3_ + tp] : 0.f;
    }
    __syncthreads();
    #pragma unroll
    for (int kk = 0; kk < 16; kk++){
      float4 a  = *(const float4*)&As[kk][ty*4];
      float4 bv = *(const float4*)&Bs[kk][tx*4];
      OUTER4(a, bv);
    }
    __syncthreads();
  }
  const size_t OFF = (size_t)B_*NM_*T3_;
  #pragma unroll
  for (int i = 0; i < 4; i++){
    int m = m0 + ty*4 + i;
    if (m >= NM_) continue;
    float bb = bias[m];
    #pragma unroll
    for (int j = 0; j < 4; j++){
      int col = col0 + tx*4 + j, b = col/T3_, t = col - b*T3_;
      size_t midx = (size_t)b*NM_*T3_ + (size_t)m*T3_ + t;
      outp[OFF + midx] = acc[i][j] + bb + outp[midx];
    }
  }
}

// ======================= host launcher =======================
extern "C" void kernel_launch(void* const* d_in, const int* in_sizes, int n_in,
                              void* d_out, int out_size){
  const int*   text = (const int*)  d_in[0];
  const float* mels = (const float*)d_in[1];
  const float* emb  = (const float*)d_in[2];
  const float* ecw  = (const float*)d_in[3];
  const float* ecb  = (const float*)d_in[4];
  const float* bng  = (const float*)d_in[5];
  const float* bnb  = (const float*)d_in[6];
  const float* Wih  = (const float*)d_in[7];
  const float* Whh  = (const float*)d_in[8];
  const float* lb   = (const float*)d_in[9];
  const float* pW1  = (const float*)d_in[10];
  const float* pb1  = (const float*)d_in[11];
  const float* pW2  = (const float*)d_in[12];
  const float* pb2  = (const float*)d_in[13];
  const float* Wq   = (const float*)d_in[14];
  const float* Wm   = (const float*)d_in[15];
  const float* Wloc = (const float*)d_in[16];
  const float* av   = (const float*)d_in[17];
  const float* dWih = (const float*)d_in[18];
  const float* dWhh = (const float*)d_in[19];
  const float* db   = (const float*)d_in[20];
  const float* oW   = (const float*)d_in[21];
  const float* ob   = (const float*)d_in[22];
  const float* pw1  = (const float*)d_in[23];
  const float* pbb1 = (const float*)d_in[24];
  const float* pg   = (const float*)d_in[25];
  const float* pbt  = (const float*)d_in[26];
  const float* pw2  = (const float*)d_in[27];
  const float* pbb2 = (const float*)d_in[28];
  float* out = (float*)d_out;

  float *h0,*hB,*Xf,*Xb,*hst,*cst,*mean,*istd,*pm,*zin,*hd,*cd,*Wc,*wl2,*post;
  float *WqT,*W1T,*W2T,*oWT;
  cudaGetSymbolAddress((void**)&h0,  g_h0);
  cudaGetSymbolAddress((void**)&hB,  g_hB);
  cudaGetSymbolAddress((void**)&Xf,  g_Xf);
  cudaGetSymbolAddress((void**)&Xb,  g_Xb);
  cudaGetSymbolAddress((void**)&hst, g_hst);
  cudaGetSymbolAddress((void**)&cst, g_cst);
  cudaGetSymbolAddress((void**)&mean,g_mean);
  cudaGetSymbolAddress((void**)&istd,g_istd);
  cudaGetSymbolAddress((void**)&pm,  g_pm);
  cudaGetSymbolAddress((void**)&zin, g_zin);
  cudaGetSymbolAddress((void**)&hd,  g_hd);
  cudaGetSymbolAddress((void**)&cd,  g_cd);
  cudaGetSymbolAddress((void**)&Wc,  g_Wc);
  cudaGetSymbolAddress((void**)&wl2, g_wl2);
  cudaGetSymbolAddress((void**)&post,g_post);
  cudaGetSymbolAddress((void**)&WqT, g_WqT);
  cudaGetSymbolAddress((void**)&W1T, g_W1T);
  cudaGetSymbolAddress((void**)&W2T, g_W2T);
  cudaGetSymbolAddress((void**)&oWT, g_oWT);

  // ---- encoder ----
  k_conv_enc<<<dim3(B_*T_/64, ENC_/64), 256>>>(text, emb, ecw, ecb, h0);
  k_bn_stats<<<512, 256>>>(h0, mean, istd, T_*B_);
  k_bn_norm<<<4096, 256>>>(h0, mean, istd, bng, bnb, (size_t)T_*B_*512);

  float* hin = h0; float* hout = hB;
  for (int l = 0; l < 3; l++){
    k_sgemm_dual<<<dim3(T_*B_/64, 16), 256>>>(hin,
        Wih + (size_t)(l*2+0)*1024*512, lb + (l*2+0)*1024, Xf,
        Wih + (size_t)(l*2+1)*1024*512, lb + (l*2+1)*1024, Xb);
    k_lstm_layer<<<dim3(16, 2, 2), 256>>>(Xf, Xb, Whh + (size_t)l*2*1024*256,
                                          hst, cst, hout);
    float* tmp = hin; hin = hout; hout = tmp;
  }
  k_sgemm<<<dim3(T_*B_/64, 2), 256>>>(hin, Wm, (const float*)0, pm, T_*B_, A_, 512);

  // ---- decoder prep ----
  k_wcomb<<<8192, 256>>>(dWih, dWhh, Wc);
  k_wl2<<<16, 256>>>(Wloc, wl2);
  k_transp<<<(128*1024+255)/256, 256>>>(Wq,  WqT, 128, 1024);
  k_transp<<<(256*80 +255)/256, 256>>>(pW1, W1T, 256, 80);
  k_transp<<<(256*256+255)/256, 256>>>(pW2, W2T, 256, 256);
  k_transp<<<(240*1536+255)/256, 256>>>(oW, oWT, 240, 1536);

  // ---- decoder (single persistent launch) ----
  k_decoder<<<128, 256>>>(mels, W1T, pb1, W2T, pb2, WqT, pm, wl2, av,
                          hin, Wc, db, oWT, ob, out,
                          zin, hd, cd, Xf);

  // ---- postnet (channel-major intermediate) ----
  k_conv_post1<<<dim3(BT3/64, 8), 256>>>(out, pw1, pbb1, post);
  k_bn_stats_cm<<<512, 256>>>(post, mean, istd);
  k_bn_norm_cm<<<dim3((BT3+255)/256, 512), 256>>>(post, mean, istd, pg, pbt);
  k_conv_post2<<<dim3(BT3/64, 2), 256>>>(post, pw2, pbb2, out);
}

// round 16
// speedup vs baseline: 1.3554x; 1.2781x over previous
#include <cuda_runtime.h>
#include <math.h>

#define B_   128
#define T_   400
#define E_   512
#define ENC_ 512
#define DEC_ 1024
#define NM_  80
#define A_   128
#define H_   256
#define T3_  1200
#define KZ_  1792
#define BT3  (B_*T3_)

typedef unsigned long long ull;

__device__ __align__(16) float g_h0 [T_*B_*ENC_];
__device__ __align__(16) float g_hB [T_*B_*ENC_];
__device__ __align__(16) float g_Xf [T_*B_*1024];
__device__ __align__(16) float g_Xb [T_*B_*1024];
__device__ __align__(16) float g_hst[2*2*B_*H_];
__device__ __align__(16) float g_cst[2*B_*H_];
__device__ float g_mean[512], g_istd[512];
__device__ __align__(16) float g_pm [T_*B_*A_];
__device__ __align__(16) float g_zin[B_*KZ_];
__device__ __align__(16) float g_hd [B_*DEC_];
__device__ __align__(16) float g_cd [2*B_*DEC_];
__device__ __align__(16) float g_Wc [4096*KZ_];
__device__ float g_wl2[A_*31];
__device__ __align__(16) float g_post[(size_t)512*BT3];
__device__ __align__(16) float g_WqT[1024*128];
__device__ __align__(16) float g_oWT[1536*240];
__device__ __align__(16) float g_zpre[(size_t)T_*B_*256];

__device__ unsigned long long g_bc64  = 0ull;
__device__ unsigned long long g_bc128 = 0ull;

__device__ __forceinline__ float sigm(float x){ return 1.f/(1.f+__expf(-x)); }
__device__ __forceinline__ float ftanh(float x){ float e = __expf(2.f*x); return 1.f - 2.f/(e+1.f); }

__device__ __forceinline__ ull pack2(float x){
  ull r; unsigned u = __float_as_uint(x);
  asm("mov.b64 %0, {%1, %1};" : "=l"(r) : "r"(u));
  return r;
}
__device__ __forceinline__ void fma2(ull& d, ull a, ull b){
  asm("fma.rn.f32x2 %0, %1, %2, %0;" : "+l"(d) : "l"(a), "l"(b));
}
__device__ __forceinline__ void unp2(float& lo, float& hi, ull v){
  unsigned a, b;
  asm("mov.b64 {%0, %1}, %2;" : "=r"(a), "=r"(b) : "l"(v));
  lo = __uint_as_float(a); hi = __uint_as_float(b);
}

__device__ __forceinline__ void gbar(unsigned long long* cnt, unsigned nb){
  __syncthreads();
  if (threadIdx.x == 0){
    __threadfence();
    unsigned long long my = atomicAdd(cnt, 1ull) + 1ull;
    unsigned long long target = ((my + nb - 1ull)/nb)*nb;
    while (*(volatile unsigned long long*)cnt < target) { }
    __threadfence();
  }
  __syncthreads();
}

#define OUTER4(a, bv) \
  acc[0][0]+=a.x*bv.x; acc[0][1]+=a.x*bv.y; acc[0][2]+=a.x*bv.z; acc[0][3]+=a.x*bv.w; \
  acc[1][0]+=a.y*bv.x; acc[1][1]+=a.y*bv.y; acc[1][2]+=a.y*bv.z; acc[1][3]+=a.y*bv.w; \
  acc[2][0]+=a.z*bv.x; acc[2][1]+=a.z*bv.y; acc[2][2]+=a.z*bv.z; acc[2][3]+=a.z*bv.w; \
  acc[3][0]+=a.w*bv.x; acc[3][1]+=a.w*bv.y; acc[3][2]+=a.w*bv.z; acc[3][3]+=a.w*bv.w;

#define POUTER4G(ac, am, bv) { \
  ull b0p=pack2(bv.x), b1p=pack2(bv.y), b2p=pack2(bv.z), b3p=pack2(bv.w); \
  fma2(ac[0][0], am.x, b0p); fma2(ac[0][1], am.y, b0p); \
  fma2(ac[1][0], am.x, b1p); fma2(ac[1][1], am.y, b1p); \
  fma2(ac[2][0], am.x, b2p); fma2(ac[2][1], am.y, b2p); \
  fma2(ac[3][0], am.x, b3p); fma2(ac[3][1], am.y, b3p); }

__global__ void k_transp(const float* __restrict__ s, float* __restrict__ d, int R, int C){
  int i = blockIdx.x*256 + threadIdx.x;
  if (i < R*C){ int r = i/C, c = i - r*C; d[c*R + r] = s[i]; }
}

// ---------------- prenet precompute ----------------
__global__ void k_pregather(const float* __restrict__ mels, float* __restrict__ pin){
  int i = blockIdx.x*256 + threadIdx.x;
  if (i < T_*B_*80){
    int r = i/80, m = i - r*80;
    int t = r >> 7, b = r & 127;
    pin[i] = (t == 0) ? 0.f : mels[((size_t)b*80 + m)*T_ + (t-1)];
  }
}

// GEMM with bias-first init + relu: C[m][n] = relu(bias[n] + sum_k A[m][k]*W[n][k])
// exact FP order of decoder prenet (bias first, k ascending)
__global__ void k_pgemm(const float* __restrict__ Am, const float* __restrict__ Wm,
                        const float* __restrict__ bias, float* __restrict__ C,
                        int M, int N, int K){
  int m0 = blockIdx.x*64, n0 = blockIdx.y*64;
  int tid = threadIdx.x, tx = tid&15, ty = tid>>4;
  __shared__ __align__(16) float As[16][64];
  __shared__ __align__(16) float Ws[16][64];
  float acc[4][4];
  #pragma unroll
  for (int i = 0; i < 4; i++)
    #pragma unroll
    for (int j = 0; j < 4; j++) acc[i][j] = bias[n0 + tx*4 + j];
  int lr = tid & 63, kg = tid >> 6;
  float4 pa = *(const float4*)&Am[(size_t)(m0+lr)*K + kg*4];
  float4 pw = *(const float4*)&Wm[(size_t)(n0+lr)*K + kg*4];
  for (int kc = 0; kc < K; kc += 16){
    As[kg*4+0][lr]=pa.x; As[kg*4+1][lr]=pa.y; As[kg*4+2][lr]=pa.z; As[kg*4+3][lr]=pa.w;
    Ws[kg*4+0][lr]=pw.x; Ws[kg*4+1][lr]=pw.y; Ws[kg*4+2][lr]=pw.z; Ws[kg*4+3][lr]=pw.w;
    __syncthreads();
    if (kc + 16 < K){
      pa = *(const float4*)&Am[(size_t)(m0+lr)*K + kc+16 + kg*4];
      pw = *(const float4*)&Wm[(size_t)(n0+lr)*K + kc+16 + kg*4];
    }
    #pragma unroll
    for (int kk = 0; kk < 16; kk++){
      float4 a  = *(const float4*)&As[kk][ty*4];
      float4 bv = *(const float4*)&Ws[kk][tx*4];
      OUTER4(a, bv);
    }
    __syncthreads();
  }
  #pragma unroll
  for (int i = 0; i < 4; i++){
    float4 v;
    v.x = fmaxf(acc[i][0], 0.f); v.y = fmaxf(acc[i][1], 0.f);
    v.z = fmaxf(acc[i][2], 0.f); v.w = fmaxf(acc[i][3], 0.f);
    *(float4*)&C[(size_t)(m0+ty*4+i)*N + n0 + tx*4] = v;
  }
}

// ---------------- encoder conv ----------
__global__ void k_conv_enc(const int* __restrict__ text, const float* __restrict__ emb,
                           const float* __restrict__ w, const float* __restrict__ bias,
                           float* __restrict__ outp){
  const int col0 = blockIdx.x*64, o0 = blockIdx.y*64;
  const int tid = threadIdx.x, tx = tid&15, ty = tid>>4;
  __shared__ int stok[64][5];
  __shared__ __align__(16) float As[16][64];
  __shared__ __align__(16) float Bs[16][64];
  for (int i = tid; i < 320; i += 256){
    int cl = i/5, k = i - cl*5;
    int col = col0 + cl, b = col/T_, t = col - b*T_;
    int tp = t + k - 2;
    stok[cl][k] = (tp >= 0 && tp < T_) ? text[b*T_ + tp] : -1;
  }
  float acc[4][4] = {};
  const int lr = tid & 63, kg = tid >> 6;
  __syncthreads();
  for (int kc = 0; kc < E_*5; kc += 16){
    float4 a4 = *(const float4*)&w[(size_t)(o0+lr)*(E_*5) + kc + kg*4];
    As[kg*4+0][lr]=a4.x; As[kg*4+1][lr]=a4.y; As[kg*4+2][lr]=a4.z; As[kg*4+3][lr]=a4.w;
    #pragma unroll
    for (int q = 0; q < 4; q++){
      int e = tid + q*256, r = e>>6, cl = e&63;
      int rg = kc + r, ii = rg/5, k = rg - ii*5;
      int tok = stok[cl][k];
      Bs[r][cl] = (tok >= 0) ? emb[tok*E_ + ii] : 0.f;
    }
    __syncthreads();
    #pragma unroll
    for (int kk = 0; kk < 16; kk++){
      float4 a  = *(const float4*)&As[kk][ty*4];
      float4 bv = *(const float4*)&Bs[kk][tx*4];
      OUTER4(a, bv);
    }
    __syncthreads();
  }
  float b0v=bias[o0+ty*4+0], b1v=bias[o0+ty*4+1], b2v=bias[o0+ty*4+2], b3v=bias[o0+ty*4+3];
  #pragma unroll
  for (int j = 0; j < 4; j++){
    int col = col0 + tx*4 + j, b = col/T_, t = col - b*T_;
    float4 v;
    v.x = fmaxf(acc[0][j]+b0v, 0.f);
    v.y = fmaxf(acc[1][j]+b1v, 0.f);
    v.z = fmaxf(acc[2][j]+b2v, 0.f);
    v.w = fmaxf(acc[3][j]+b3v, 0.f);
    *(float4*)&outp[(size_t)(t*B_+b)*ENC_ + o0 + ty*4] = v;
  }
}

// ---------------- encoder BN ----------
__global__ void k_bn_stats(const float* __restrict__ x, float* mean, float* istd, int rows){
  int o = blockIdx.x, tid = threadIdx.x;
  float s = 0.f, ss = 0.f;
  for (int r = tid; r < rows; r += 256){
    float v = x[(size_t)r*512 + o]; s += v; ss += v*v;
  }
  __shared__ float rs[256], rq[256];
  rs[tid]=s; rq[tid]=ss; __syncthreads();
  for (int st = 128; st; st >>= 1){
    if (tid < st){ rs[tid]+=rs[tid+st]; rq[tid]+=rq[tid+st]; }
    __syncthreads();
  }
  if (tid == 0){
    float m = rs[0]/(float)rows;
    float var = rq[0]/(float)rows - m*m;
    mean[o] = m; istd[o] = rsqrtf(var + 1e-5f);
  }
}
__global__ void k_bn_norm(float* x, const float* mean, const float* istd,
                          const float* g, const float* bt, size_t n){
  size_t i = (size_t)blockIdx.x*256 + threadIdx.x, s = (size_t)gridDim.x*256;
  for (; i < n; i += s){
    int o = (int)(i & 511);
    x[i] = (x[i]-mean[o])*istd[o]*g[o] + bt[o];
  }
}

// ---------------- postnet BN (channel-major) ----------
__global__ void k_bn_stats_cm(const float* __restrict__ x, float* mean, float* istd){
  int o = blockIdx.x, tid = threadIdx.x;
  const float* row = x + (size_t)o*BT3;
  float s = 0.f, ss = 0.f;
  for (int i = tid; i < BT3; i += 256){ float v = row[i]; s += v; ss += v*v; }
  __shared__ float rs[256], rq[256];
  rs[tid]=s; rq[tid]=ss; __syncthreads();
  for (int st = 128; st; st >>= 1){
    if (tid < st){ rs[tid]+=rs[tid+st]; rq[tid]+=rq[tid+st]; }
    __syncthreads();
  }
  if (tid == 0){
    float m = rs[0]/(float)BT3;
    float var = rq[0]/(float)BT3 - m*m;
    mean[o] = m; istd[o] = rsqrtf(var + 1e-5f);
  }
}
__global__ void k_bn_norm_cm(float* x, const float* mean, const float* istd,
                             const float* g, const float* bt){
  int o = blockIdx.y;
  int i = blockIdx.x*256 + threadIdx.x;
  if (i < BT3){
    size_t idx = (size_t)o*BT3 + i;
    float v = (x[idx]-mean[o])*istd[o]*g[o] + bt[o];
    x[idx] = ftanh(v);
  }
}

// ---------------- SGEMM (f32x2 packed) ------
__global__ void k_sgemm(const float* __restrict__ Am, const float* __restrict__ Wm,
                        const float* __restrict__ bias, float* __restrict__ C,
                        int M, int N, int K){
  int m0 = blockIdx.x*64, n0 = blockIdx.y*64;
  int tid = threadIdx.x, tx = tid&15, ty = tid>>4;
  __shared__ __align__(16) float As[16][64];
  __shared__ __align__(16) float Ws[16][64];
  ull ac2[4][2];
  #pragma unroll
  for (int i=0;i<4;i++){ ac2[i][0]=0ull; ac2[i][1]=0ull; }
  int lr = tid & 63, kg = tid >> 6;
  float4 pa = *(const float4*)&Am[(size_t)(m0+lr)*K + kg*4];
  float4 pw = *(const float4*)&Wm[(size_t)(n0+lr)*K + kg*4];
  for (int kc = 0; kc < K; kc += 16){
    As[kg*4+0][lr]=pa.x; As[kg*4+1][lr]=pa.y; As[kg*4+2][lr]=pa.z; As[kg*4+3][lr]=pa.w;
    Ws[kg*4+0][lr]=pw.x; Ws[kg*4+1][lr]=pw.y; Ws[kg*4+2][lr]=pw.z; Ws[kg*4+3][lr]=pw.w;
    __syncthreads();
    if (kc + 16 < K){
      pa = *(const float4*)&Am[(size_t)(m0+lr)*K + kc+16 + kg*4];
      pw = *(const float4*)&Wm[(size_t)(n0+lr)*K + kc+16 + kg*4];
    }
    #pragma unroll
    for (int kk = 0; kk < 16; kk++){
      ulonglong2 am = *(const ulonglong2*)&As[kk][ty*4];
      float4 bv = *(const float4*)&Ws[kk][tx*4];
      POUTER4G(ac2, am, bv);
    }
    __syncthreads();
  }
  float bb[4] = {0,0,0,0};
  if (bias){ bb[0]=bias[n0+tx*4+0]; bb[1]=bias[n0+tx*4+1]; bb[2]=bias[n0+tx*4+2]; bb[3]=bias[n0+tx*4+3]; }
  float r[4][4];
  #pragma unroll
  for (int j = 0; j < 4; j++){
    unp2(r[0][j], r[1][j], ac2[j][0]);
    unp2(r[2][j], r[3][j], ac2[j][1]);
  }
  #pragma unroll
  for (int i = 0; i < 4; i++){
    float4 v; v.x=r[i][0]+bb[0]; v.y=r[i][1]+bb[1]; v.z=r[i][2]+bb[2]; v.w=r[i][3]+bb[3];
    *(float4*)&C[(size_t)(m0+ty*4+i)*N + n0 + tx*4] = v;
  }
}

// ---------------- dual SGEMM ------
__global__ void k_sgemm_dual(const float* __restrict__ Am,
                             const float* __restrict__ Wf, const float* __restrict__ bf, float* __restrict__ Cf,
                             const float* __restrict__ Wb, const float* __restrict__ bb_, float* __restrict__ Cb){
  const int K = 512, N = 1024;
  int m0 = blockIdx.x*64, n0 = blockIdx.y*64;
  int tid = threadIdx.x, tx = tid&15, ty = tid>>4;
  __shared__ __align__(16) float As[16*64];
  __shared__ __align__(16) float Wsf[16*64];
  __shared__ __align__(16) float Wsb[16*64];
  ull acf[4][2], acb[4][2];
  #pragma unroll
  for (int i=0;i<4;i++){ acf[i][0]=0; acf[i][1]=0; acb[i][0]=0; acb[i][1]=0; }
  int lr = tid & 63, kg = tid >> 6;
  float4 pa = *(const float4*)&Am[(size_t)(m0+lr)*K + kg*4];
  float4 pf = *(const float4*)&Wf[(size_t)(n0+lr)*K + kg*4];
  float4 pb = *(const float4*)&Wb[(size_t)(n0+lr)*K + kg*4];
  for (int kc = 0; kc < K; kc += 16){
    As [(kg*4+0)*64+lr]=pa.x; As [(kg*4+1)*64+lr]=pa.y; As [(kg*4+2)*64+lr]=pa.z; As [(kg*4+3)*64+lr]=pa.w;
    Wsf[(kg*4+0)*64+lr]=pf.x; Wsf[(kg*4+1)*64+lr]=pf.y; Wsf[(kg*4+2)*64+lr]=pf.z; Wsf[(kg*4+3)*64+lr]=pf.w;
    Wsb[(kg*4+0)*64+lr]=pb.x; Wsb[(kg*4+1)*64+lr]=pb.y; Wsb[(kg*4+2)*64+lr]=pb.z; Wsb[(kg*4+3)*64+lr]=pb.w;
    __syncthreads();
    if (kc + 16 < K){
      pa = *(const float4*)&Am[(size_t)(m0+lr)*K + kc+16 + kg*4];
      pf = *(const float4*)&Wf[(size_t)(n0+lr)*K + kc+16 + kg*4];
      pb = *(const float4*)&Wb[(size_t)(n0+lr)*K + kc+16 + kg*4];
    }
    #pragma unroll
    for (int kk = 0; kk < 16; kk++){
      ulonglong2 am = *(const ulonglong2*)&As[kk*64 + ty*4];
      float4 bvf = *(const float4*)&Wsf[kk*64 + tx*4];
      POUTER4G(acf, am, bvf);
      float4 bvb = *(const float4*)&Wsb[kk*64 + tx*4];
      POUTER4G(acb, am, bvb);
    }
    __syncthreads();
  }
  float bfv[4] = {bf[n0+tx*4+0], bf[n0+tx*4+1], bf[n0+tx*4+2], bf[n0+tx*4+3]};
  float bbv[4] = {bb_[n0+tx*4+0], bb_[n0+tx*4+1], bb_[n0+tx*4+2], bb_[n0+tx*4+3]};
  float rf[4][4], rb[4][4];
  #pragma unroll
  for (int j = 0; j < 4; j++){
    unp2(rf[0][j], rf[1][j], acf[j][0]); unp2(rf[2][j], rf[3][j], acf[j][1]);
    unp2(rb[0][j], rb[1][j], acb[j][0]); unp2(rb[2][j], rb[3][j], acb[j][1]);
  }
  #pragma unroll
  for (int i = 0; i < 4; i++){
    float4 v1; v1.x=rf[i][0]+bfv[0]; v1.y=rf[i][1]+bfv[1]; v1.z=rf[i][2]+bfv[2]; v1.w=rf[i][3]+bfv[3];
    *(float4*)&Cf[(size_t)(m0+ty*4+i)*N + n0 + tx*4] = v1;
    float4 v2; v2.x=rb[i][0]+bbv[0]; v2.y=rb[i][1]+bbv[1]; v2.z=rb[i][2]+bbv[2]; v2.w=rb[i][3]+bbv[3];
    *(float4*)&Cb[(size_t)(m0+ty*4+i)*N + n0 + tx*4] = v2;
  }
}

// ---------------- persistent biLSTM layer ----------
__global__ void k_lstm_layer(const float* __restrict__ Xf, const float* __restrict__ Xb,
                             const float* __restrict__ Whh_base,
                             float* __restrict__ hst, float* __restrict__ cst,
                             float* __restrict__ hout){
  const int jt = blockIdx.x, bt = blockIdx.y, dir = blockIdx.z;
  const int tid = threadIdx.x, tx = tid&15, ty = tid>>4;
  const int b0 = bt*64, j0 = jt*16;
  const float* Whh = Whh_base + (size_t)dir*4*H_*H_;
  const float* Xg  = dir ? Xb : Xf;
  __shared__ __align__(16) float hs[16][64];
  __shared__ __align__(16) float ws[16][64];
  const int lr = tid & 63, kg = tid >> 6;
  const int wrow = (lr&3)*H_ + j0 + (lr>>2);

  for (int i = tid; i < 64*16; i += 256){
    int bb = b0 + (i>>4), j = j0 + (i&15);
    hst[(size_t)(0*2+dir)*B_*H_ + bb*H_ + j] = 0.f;
    hst[(size_t)(1*2+dir)*B_*H_ + bb*H_ + j] = 0.f;
    cst[(size_t)dir*B_*H_ + bb*H_ + j] = 0.f;
  }
  gbar(&g_bc64, 64);

  for (int t = 0; t < T_; t++){
    const float* hprev = hst + (size_t)((t&1)*2 + dir)*B_*H_;
    float* hnext       = hst + (size_t)(((t+1)&1)*2 + dir)*B_*H_;
    float acc[4][4] = {};
    float4 ph = *(const float4*)&hprev[(size_t)(b0+lr)*H_ + kg*4];
    float4 pw = *(const float4*)&Whh[(size_t)wrow*H_ + kg*4];
    for (int kc = 0; kc < H_; kc += 16){
      hs[kg*4+0][lr]=ph.x; hs[kg*4+1][lr]=ph.y; hs[kg*4+2][lr]=ph.z; hs[kg*4+3][lr]=ph.w;
      ws[kg*4+0][lr]=pw.x; ws[kg*4+1][lr]=pw.y; ws[kg*4+2][lr]=pw.z; ws[kg*4+3][lr]=pw.w;
      __syncthreads();
      if (kc + 16 < H_){
        ph = *(const float4*)&hprev[(size_t)(b0+lr)*H_ + kc+16 + kg*4];
        pw = *(const float4*)&Whh[(size_t)wrow*H_ + kc+16 + kg*4];
      }
      #pragma unroll
      for (int kk = 0; kk < 16; kk++){
        float4 a  = *(const float4*)&hs[kk][ty*4];
        float4 bv = *(const float4*)&ws[kk][tx*4];
        OUTER4(a, bv);
      }
      __syncthreads();
    }
    const int teff = dir ? (T_-1-t) : t;
    const int j = j0 + tx;
    #pragma unroll
    for (int i = 0; i < 4; i++){
      int bb = b0 + ty*4 + i;
      const float* xg = Xg + (size_t)(teff*B_ + bb)*1024;
      float gi = acc[i][0] + xg[j];
      float gf = acc[i][1] + xg[H_ + j];
      float gc = acc[i][2] + xg[2*H_ + j];
      float go = acc[i][3] + xg[3*H_ + j];
      size_t ci = (size_t)dir*B_*H_ + (size_t)bb*H_ + j;
      float c = cst[ci];
      c = sigm(gf)*c + sigm(gi)*ftanh(gc);
      float hv = sigm(go)*ftanh(c);
      cst[ci] = c;
      hnext[(size_t)bb*H_ + j] = hv;
      hout[(size_t)(teff*B_ + bb)*ENC_ + dir*H_ + j] = hv;
    }
    gbar(&g_bc64, 64);
  }
}

__global__ void k_wcomb(const float* __restrict__ wih, const float* __restrict__ whh,
                        float* __restrict__ wc){
  size_t i = (size_t)blockIdx.x*256 + threadIdx.x, s = (size_t)gridDim.x*256;
  for (; i < (size_t)4096*KZ_; i += s){
    int n = (int)(i / KZ_), k = (int)(i - (size_t)n*KZ_);
    wc[i] = (k < 768) ? wih[(size_t)n*768 + k] : whh[(size_t)n*1024 + (k-768)];
  }
}
__global__ void k_wl2(const float* __restrict__ wl, float* __restrict__ w2){
  int i = blockIdx.x*256 + threadIdx.x;
  if (i < A_*31){ int a = i/31, k = i - a*31; w2[i] = wl[a*62 + k] + wl[a*62 + 31 + k]; }
}

// ---------------- persistent decoder: 512 threads/block ----------
// smem (floats): s_hd 0..1024 | s_sv 0..8448 | s_sp 8448..8960 | s_c 8960..9406
// s_pq 9406..9534 | s_e 9536..9936 | s_al 0..400 | s_red 448..704
// P4 As 0..1024 Ws 1024..2048 | P56 z 0..6176 | s_cum 10000..10400
__global__ void __launch_bounds__(512, 1)
k_decoder(const float* __restrict__ zpre,
          const float* __restrict__ WqT, const float* __restrict__ pm,
          const float* __restrict__ wl2, const float* __restrict__ av,
          const float* __restrict__ mem, const float* __restrict__ Wc,
          const float* __restrict__ db,  const float* __restrict__ oWT,
          const float* __restrict__ ob,  float* __restrict__ out,
          float* __restrict__ zin, float* __restrict__ hd,
          float* __restrict__ cd, float* __restrict__ gates){
  __shared__ __align__(16) float sh[10400];
  const int tid = threadIdx.x;
  const int blk = blockIdx.x;
  const int b = blk;
  float* s_cum = sh + 10000;

  float wl[31]; float va_r;
  {
    int a = tid & 127;
    #pragma unroll
    for (int k = 0; k < 31; k++) wl[k] = wl2[a*31 + k];
    va_r = av[a];
  }

  for (int i = tid; i < T_; i += 512) s_cum[i] = 0.f;
  for (int i = tid; i < DEC_; i += 512){
    hd[(size_t)b*DEC_+i] = 0.f;
    cd[(size_t)b*DEC_+i] = 0.f;
    cd[(size_t)(B_+b)*DEC_+i] = 0.f;
  }
  gbar(&g_bc128, 128);

  for (int t = 0; t < T_; t++){
    const float* cdo = cd + (size_t)(t&1)*B_*DEC_;
    float*       cdn = cd + (size_t)((t+1)&1)*B_*DEC_;

    // ===== P123 =====
    {
      float* s_hd = sh;
      float* s_c  = sh + 8960;
      float* s_pq = sh + 9406;
      for (int i = tid; i < DEC_; i += 512){
        float v = hd[(size_t)b*DEC_ + i];
        s_hd[i] = v; zin[(size_t)b*KZ_ + 768 + i] = v;
      }
      __syncthreads();
      // warps 0-3: pq dot ; warps 4-15: s_c staging + prenet copy
      if (tid < 128){
        float acc = 0.f;
        #pragma unroll 16
        for (int k = 0; k < DEC_; k++) acc += WqT[k*128 + tid]*s_hd[k];
        s_pq[tid] = acc;
      } else {
        int t2 = tid - 128;
        for (int i = t2; i < 446; i += 384){
          int tt = i - 15;
          s_c[i] = (tt >= 0 && tt < T_) ? s_cum[tt] : 0.f;
        }
        if (t2 < 256) zin[(size_t)b*KZ_ + t2] = zpre[((size_t)t*B_ + b)*256 + t2];
      }
      __syncthreads();

      // energy: 4 sub-groups, 7 iterations
      float* s_sv = sh;
      float* s_sp = sh + 8448;
      float* s_e  = sh + 9536;
      const int sub = tid >> 7, a = tid & 127;
      const float pqa = s_pq[a];
      for (int it = 0; it < 7; it++){
        int chunk = it*4 + sub;
        if (chunk < 25){
          int t0 = chunk*16;
          #pragma unroll
          for (int j = 0; j < 16; j++){
            float pl = 0.f;
            #pragma unroll
            for (int k = 0; k < 31; k++) pl += wl[k]*s_c[t0 + j + k];
            float x = pqa + pm[(size_t)((t0+j)*B_ + b)*A_ + a] + pl;
            s_sv[(sub*16 + j)*132 + a] = va_r * ftanh(x);
          }
        }
        __syncthreads();
        {
          int r = tid >> 3, l = tid & 7;
          int chr = it*4 + (r >> 4);
          if (chr < 25){
            float p = 0.f;
            #pragma unroll
            for (int k = 0; k < 16; k++) p += s_sv[r*132 + l*16 + k];
            s_sp[r*8 + l] = p;
          }
        }
        __syncthreads();
        if (tid < 64){
          int chr = it*4 + (tid >> 4), jr = tid & 15;
          if (chr < 25){
            float s = 0.f;
            #pragma unroll
            for (int q = 0; q < 8; q++) s += s_sp[tid*8 + q];
            s_e[chr*16 + jr] = s;
          }
        }
        __syncthreads();
      }

      // softmax + cum (identical 256-thread reduction tree)
      float* s_al  = sh;
      float* s_red = sh + 448;
      float v0 = 0.f, v1 = 0.f, e0 = 0.f, e1 = 0.f;
      if (tid < 256){
        v0 = s_e[tid];
        v1 = (tid + 256 < T_) ? s_e[tid + 256] : -1e30f;
        s_red[tid] = fmaxf(v0, v1);
      }
      __syncthreads();
      for (int s = 128; s; s >>= 1){ if (tid < s) s_red[tid] = fmaxf(s_red[tid], s_red[tid+s]); __syncthreads(); }
      float mx = s_red[0];
      __syncthreads();
      if (tid < 256){
        e0 = __expf(v0 - mx);
        e1 = (tid + 256 < T_) ? __expf(v1 - mx) : 0.f;
        s_red[tid] = e0 + e1;
      }
      __syncthreads();
      for (int s = 128; s; s >>= 1){ if (tid < s) s_red[tid] += s_red[tid+s]; __syncthreads(); }
      float inv = 1.f/s_red[0];
      if (tid < 256){
        float a0 = e0*inv;
        s_al[tid] = a0; s_cum[tid] += a0;
        if (tid + 256 < T_){
          float a1v = e1*inv;
          s_al[tid+256] = a1v; s_cum[tid+256] += a1v;
        }
      }
      __syncthreads();

      // context: 512 threads, one column each (t-order unchanged)
      float c0 = 0.f;
      const float* memc = mem + (size_t)b*ENC_ + tid;
      #pragma unroll 16
      for (int tt = 0; tt < T_; tt++)
        c0 += s_al[tt]*memc[(size_t)tt*B_*ENC_];
      zin[(size_t)b*KZ_ + 256 + tid] = c0;
    }
    gbar(&g_bc128, 128);

    // ===== P4: cell GEMM (256 threads, named barrier) =====
    if (tid < 256){
      const int m0 = (blk & 1)*64, n0 = (blk >> 1)*64;
      const int tx = tid&15, ty = tid>>4;
      float* As = sh;
      float* Ws = sh + 1024;
      ull ac2[4][2];
      #pragma unroll
      for (int i=0;i<4;i++){ ac2[i][0]=0ull; ac2[i][1]=0ull; }
      const int lr = tid & 63, kg = tid >> 6;
      const float* Arow = zin + (size_t)(m0+lr)*KZ_ + kg*4;
      const float* Wrow = Wc  + (size_t)(n0+lr)*KZ_ + kg*4;
      float4 pa0 = *(const float4*)(Arow);
      float4 pw0 = *(const float4*)(Wrow);
      float4 pa1 = *(const float4*)(Arow + 16);
      float4 pw1 = *(const float4*)(Wrow + 16);
      for (int kc = 0; kc < KZ_; kc += 16){
        As[(kg*4+0)*64+lr]=pa0.x; As[(kg*4+1)*64+lr]=pa0.y; As[(kg*4+2)*64+lr]=pa0.z; As[(kg*4+3)*64+lr]=pa0.w;
        Ws[(kg*4+0)*64+lr]=pw0.x; Ws[(kg*4+1)*64+lr]=pw0.y; Ws[(kg*4+2)*64+lr]=pw0.z; Ws[(kg*4+3)*64+lr]=pw0.w;
        asm volatile("bar.sync 2, 256;" ::: "memory");
        pa0 = pa1; pw0 = pw1;
        if (kc + 32 < KZ_){
          pa1 = *(const float4*)(Arow + kc + 32);
          pw1 = *(const float4*)(Wrow + kc + 32);
        }
        #pragma unroll
        for (int kk = 0; kk < 16; kk++){
          ulonglong2 am = *(const ulonglong2*)&As[kk*64 + ty*4];
          float4 bv = *(const float4*)&Ws[kk*64 + tx*4];
          POUTER4G(ac2, am, bv);
        }
        asm volatile("bar.sync 2, 256;" ::: "memory");
      }
      float bb[4] = {db[n0+tx*4+0], db[n0+tx*4+1], db[n0+tx*4+2], db[n0+tx*4+3]};
      float r[4][4];
      #pragma unroll
      for (int j = 0; j < 4; j++){
        unp2(r[0][j], r[1][j], ac2[j][0]);
        unp2(r[2][j], r[3][j], ac2[j][1]);
      }
      #pragma unroll
      for (int i = 0; i < 4; i++){
        float4 v; v.x=r[i][0]+bb[0]; v.y=r[i][1]+bb[1]; v.z=r[i][2]+bb[2]; v.w=r[i][3]+bb[3];
        *(float4*)&gates[(size_t)(m0+ty*4+i)*4096 + n0 + tx*4] = v;
      }
    }
    gbar(&g_bc128, 128);

    // ===== P56: cell + outproj =====
    {
      int j = tid*2;
      float2 gi = *(const float2*)&gates[(size_t)b*4096 + j];
      float2 gf = *(const float2*)&gates[(size_t)b*4096 + 1024 + j];
      float2 gc = *(const float2*)&gates[(size_t)b*4096 + 2048 + j];
      float2 go = *(const float2*)&gates[(size_t)b*4096 + 3072 + j];
      float2 c  = *(const float2*)&cdo[(size_t)b*DEC_ + j];
      float2 hn;
      c.x = sigm(gf.x)*c.x + sigm(gi.x)*ftanh(gc.x); hn.x = sigm(go.x)*ftanh(c.x);
      c.y = sigm(gf.y)*c.y + sigm(gi.y)*ftanh(gc.y); hn.y = sigm(go.y)*ftanh(c.y);
      *(float2*)&cdn[(size_t)b*DEC_ + j] = c;
      *(float2*)&hd[(size_t)b*DEC_ + j] = hn;

      if (blk < 32){
        float* z = sh;  // [4][1544]
        #pragma unroll
        for (int bi = 0; bi < 4; bi++){
          int b2 = blk*4 + bi;
          float2 gi2 = *(const float2*)&gates[(size_t)b2*4096 + j];
          float2 gf2 = *(const float2*)&gates[(size_t)b2*4096 + 1024 + j];
          float2 gc2 = *(const float2*)&gates[(size_t)b2*4096 + 2048 + j];
          float2 go2 = *(const float2*)&gates[(size_t)b2*4096 + 3072 + j];
          float2 c2  = *(const float2*)&cdo[(size_t)b2*DEC_ + j];
          float2 h2;
          c2.x = sigm(gf2.x)*c2.x + sigm(gi2.x)*ftanh(gc2.x); h2.x = sigm(go2.x)*ftanh(c2.x);
          c2.y = sigm(gf2.y)*c2.y + sigm(gi2.y)*ftanh(gc2.y); h2.y = sigm(go2.y)*ftanh(c2.y);
          z[bi*1544 + j]     = h2.x;
          z[bi*1544 + j + 1] = h2.y;
        }
        for (int i = tid; i < 4*512; i += 512){
          int bi = i >> 9, kk = i & 511;
          z[bi*1544 + 1024 + kk] = zin[(size_t)(blk*4+bi)*KZ_ + 256 + kk];
        }
        __syncthreads();
        if (tid < 480){
          int n = tid >> 1, pr = tid & 1;
          const float* z0 = z + (pr*2)*1544;
          const float* z1 = z + (pr*2+1)*1544;
          float a0 = 0.f, a1 = 0.f;
          #pragma unroll 16
          for (int k = 0; k < 1536; k++){
            float wv = oWT[k*240 + n];
            a0 += wv*z0[k]; a1 += wv*z1[k];
          }
          float bb = ob[n];
          int r = n / NM_, m = n - r*NM_;
          float vv[2] = {a0+bb, a1+bb};
          #pragma unroll
          for (int q = 0; q < 2; q++){
            int b2 = blk*4 + pr*2 + q;
            float val = vv[q];
            out[(size_t)b2*NM_*T3_ + (size_t)m*T3_ + 3*t + r] = val;
            if (m == NM_-1)
              out[(size_t)2*B_*NM_*T3_ + (size_t)b2*T3_ + 3*t + r] = sigm(val);
          }
        }
      }
      __syncthreads();  // order hd/cd writes before next step's reads
    }
  }
}

// ---------------- postnet conv1 (channel-major out) ------
__global__ void k_conv_post1(const float* __restrict__ mel, const float* __restrict__ w,
                             const float* __restrict__ bias, float* __restrict__ outp){
  const int col0 = blockIdx.x*64, o0 = blockIdx.y*64;
  const int tid = threadIdx.x, tx = tid&15, ty = tid>>4;
  __shared__ __align__(16) float As[16][64];
  __shared__ __align__(16) float Bs[16][64];
  float acc[4][4] = {};
  const int lr = tid & 63, kg = tid >> 6;
  for (int kc = 0; kc < NM_*5; kc += 16){
    float4 a4 = *(const float4*)&w[(size_t)(o0+lr)*(NM_*5) + kc + kg*4];
    As[kg*4+0][lr]=a4.x; As[kg*4+1][lr]=a4.y; As[kg*4+2][lr]=a4.z; As[kg*4+3][lr]=a4.w;
    #pragma unroll
    for (int q = 0; q < 4; q++){
      int e = tid + q*256, r = e>>6, cl = e&63;
      int rg = kc + r, m = rg/5, k = rg - m*5;
      int col = col0 + cl, b = col/T3_, t = col - b*T3_;
      int tp = t + k - 2;
      Bs[r][cl] = (tp >= 0 && tp < T3_) ? mel[(size_t)b*NM_*T3_ + (size_t)m*T3_ + tp] : 0.f;
    }
    __syncthreads();
    #pragma unroll
    for (int kk = 0; kk < 16; kk++){
      float4 a  = *(const float4*)&As[kk][ty*4];
      float4 bv = *(const float4*)&Bs[kk][tx*4];
      OUTER4(a, bv);
    }
    __syncthreads();
  }
  #pragma unroll
  for (int i = 0; i < 4; i++){
    int o = o0 + ty*4 + i;
    float bv = bias[o];
    #pragma unroll
    for (int j = 0; j < 4; j++){
      int col = col0 + tx*4 + j;
      outp[(size_t)o*BT3 + col] = acc[i][j] + bv;
    }
  }
}

// ---------------- postnet conv2 + residual ------
__global__ void k_conv_post2(const float* __restrict__ q, const float* __restrict__ w2,
                             const float* __restrict__ bias, float* __restrict__ outp){
  const int col0 = blockIdx.x*64, m0 = blockIdx.y*64;
  const int tid = threadIdx.x, tx = tid&15, ty = tid>>4;
  __shared__ __align__(16) float As[16][64];
  __shared__ __align__(16) float Bs[16][64];
  float acc[4][4] = {};
  const int lr = tid & 63, kg = tid >> 6;
  const int row = m0 + lr;
  for (int kc = 0; kc < 2560; kc += 16){
    float4 a4 = make_float4(0.f,0.f,0.f,0.f);
    if (row < NM_) a4 = *(const float4*)&w2[(size_t)row*2560 + kc + kg*4];
    As[kg*4+0][lr]=a4.x; As[kg*4+1][lr]=a4.y; As[kg*4+2][lr]=a4.z; As[kg*4+3][lr]=a4.w;
    #pragma unroll
    for (int qq = 0; qq < 4; qq++){
      int e = tid + qq*256, r = e>>6, cl = e&63;
      int rg = kc + r, o = rg/5, k = rg - o*5;
      int col = col0 + cl, b = col/T3_, t = col - b*T3_;
      int tp = t + k - 2;
      Bs[r][cl] = (tp >= 0 && tp < T3_) ? q[(size_t)o*BT3 + b*T3_ + tp] : 0.f;
    }
    __syncthreads();
    #pragma unroll
    for (int kk = 0; kk < 16; kk++){
      float4 a  = *(const float4*)&As[kk][ty*4];
      float4 bv = *(const float4*)&Bs[kk][tx*4];
      OUTER4(a, bv);
    }
    __syncthreads();
  }
  const size_t OFF = (size_t)B_*NM_*T3_;
  #pragma unroll
  for (int i = 0; i < 4; i++){
    int m = m0 + ty*4 + i;
    if (m >= NM_) continue;
    float bb = bias[m];
    #pragma unroll
    for (int j = 0; j < 4; j++){
      int col = col0 + tx*4 + j, b = col/T3_, t = col - b*T3_;
      size_t midx = (size_t)b*NM_*T3_ + (size_t)m*T3_ + t;
      outp[OFF + midx] = acc[i][j] + bb + outp[midx];
    }
  }
}

// ======================= host launcher =======================
extern "C" void kernel_launch(void* const* d_in, const int* in_sizes, int n_in,
                              void* d_out, int out_size){
  const int*   text = (const int*)  d_in[0];
  const float* mels = (const float*)d_in[1];
  const float* emb  = (const float*)d_in[2];
  const float* ecw  = (const float*)d_in[3];
  const float* ecb  = (const float*)d_in[4];
  const float* bng  = (const float*)d_in[5];
  const float* bnb  = (const float*)d_in[6];
  const float* Wih  = (const float*)d_in[7];
  const float* Whh  = (const float*)d_in[8];
  const float* lb   = (const float*)d_in[9];
  const float* pW1  = (const float*)d_in[10];
  const float* pb1  = (const float*)d_in[11];
  const float* pW2  = (const float*)d_in[12];
  const float* pb2  = (const float*)d_in[13];
  const float* Wq   = (const float*)d_in[14];
  const float* Wm   = (const float*)d_in[15];
  const float* Wloc = (const float*)d_in[16];
  const float* av   = (const float*)d_in[17];
  const float* dWih = (const float*)d_in[18];
  const float* dWhh = (const float*)d_in[19];
  const float* db   = (const float*)d_in[20];
  const float* oW   = (const float*)d_in[21];
  const float* ob   = (const float*)d_in[22];
  const float* pw1  = (const float*)d_in[23];
  const float* pbb1 = (const float*)d_in[24];
  const float* pg   = (const float*)d_in[25];
  const float* pbt  = (const float*)d_in[26];
  const float* pw2  = (const float*)d_in[27];
  const float* pbb2 = (const float*)d_in[28];
  float* out = (float*)d_out;

  float *h0,*hB,*Xf,*Xb,*hst,*cst,*mean,*istd,*pm,*zin,*hd,*cd,*Wc,*wl2,*post;
  float *WqT,*oWT,*zpre;
  cudaGetSymbolAddress((void**)&h0,  g_h0);
  cudaGetSymbolAddress((void**)&hB,  g_hB);
  cudaGetSymbolAddress((void**)&Xf,  g_Xf);
  cudaGetSymbolAddress((void**)&Xb,  g_Xb);
  cudaGetSymbolAddress((void**)&hst, g_hst);
  cudaGetSymbolAddress((void**)&cst, g_cst);
  cudaGetSymbolAddress((void**)&mean,g_mean);
  cudaGetSymbolAddress((void**)&istd,g_istd);
  cudaGetSymbolAddress((void**)&pm,  g_pm);
  cudaGetSymbolAddress((void**)&zin, g_zin);
  cudaGetSymbolAddress((void**)&hd,  g_hd);
  cudaGetSymbolAddress((void**)&cd,  g_cd);
  cudaGetSymbolAddress((void**)&Wc,  g_Wc);
  cudaGetSymbolAddress((void**)&wl2, g_wl2);
  cudaGetSymbolAddress((void**)&post,g_post);
  cudaGetSymbolAddress((void**)&WqT, g_WqT);
  cudaGetSymbolAddress((void**)&oWT, g_oWT);
  cudaGetSymbolAddress((void**)&zpre,g_zpre);

  // ---- prenet precompute (independent of encoder) ----
  k_pregather<<<(T_*B_*80+255)/256, 256>>>(mels, Xb);
  k_pgemm<<<dim3(T_*B_/64, 4), 256>>>(Xb, pW1, pb1, Xf, T_*B_, 256, 80);
  k_pgemm<<<dim3(T_*B_/64, 4), 256>>>(Xf, pW2, pb2, zpre, T_*B_, 256, 256);

  // ---- encoder ----
  k_conv_enc<<<dim3(B_*T_/64, ENC_/64), 256>>>(text, emb, ecw, ecb, h0);
  k_bn_stats<<<512, 256>>>(h0, mean, istd, T_*B_);
  k_bn_norm<<<4096, 256>>>(h0, mean, istd, bng, bnb, (size_t)T_*B_*512);

  float* hin = h0; float* hout = hB;
  for (int l = 0; l < 3; l++){
    k_sgemm_dual<<<dim3(T_*B_/64, 16), 256>>>(hin,
        Wih + (size_t)(l*2+0)*1024*512, lb + (l*2+0)*1024, Xf,
        Wih + (size_t)(l*2+1)*1024*512, lb + (l*2+1)*1024, Xb);
    k_lstm_layer<<<dim3(16, 2, 2), 256>>>(Xf, Xb, Whh + (size_t)l*2*1024*256,
                                          hst, cst, hout);
    float* tmp = hin; hin = hout; hout = tmp;
  }
  k_sgemm<<<dim3(T_*B_/64, 2), 256>>>(hin, Wm, (const float*)0, pm, T_*B_, A_, 512);

  // ---- decoder prep ----
  k_wcomb<<<8192, 256>>>(dWih, dWhh, Wc);
  k_wl2<<<16, 256>>>(Wloc, wl2);
  k_transp<<<(128*1024+255)/256, 256>>>(Wq,  WqT, 128, 1024);
  k_transp<<<(240*1536+255)/256, 256>>>(oW, oWT, 240, 1536);

  // ---- decoder (single persistent launch, 512 threads) ----
  k_decoder<<<128, 512>>>(zpre, WqT, pm, wl2, av,
                          hin, Wc, db, oWT, ob, out,
                          zin, hd, cd, Xf);

  // ---- postnet (channel-major intermediate) ----
  k_conv_post1<<<dim3(BT3/64, 8), 256>>>(out, pw1, pbb1, post);
  k_bn_stats_cm<<<512, 256>>>(post, mean, istd);
  k_bn_norm_cm<<<dim3((BT3+255)/256, 512), 256>>>(post, mean, istd, pg, pbt);
  k_conv_post2<<<dim3(BT3/64, 2), 256>>>(post, pw2, pbb2, out);
}